// round 7
// baseline (speedup 1.0000x reference)
#include <cuda_runtime.h>
#include <cuda_bf16.h>
#include <math.h>
#include <stdint.h>

#define HID 128
#define NPIX (4*256*256)
#define NL 4
#define NTILES 2048
#define GRID 304            // 2 CTAs per SM
#define THREADS 256

// ---------------------------------------------------------------------------
// Device globals: activations as bf16 hi/lo pairs (exact fp32 split)
// ---------------------------------------------------------------------------
__device__ unsigned short g_h0[(size_t)NPIX * HID];
__device__ unsigned short g_l0[(size_t)NPIX * HID];
__device__ unsigned short g_h1[(size_t)NPIX * HID];
__device__ unsigned short g_l1[(size_t)NPIX * HID];
__device__ unsigned short g_whi[NL * 4 * 8192];
__device__ unsigned short g_wlo[NL * 4 * 8192];
__device__ float g_sx[256];

// ---------------------------------------------------------------------------
// Helpers
// ---------------------------------------------------------------------------
__device__ __forceinline__ uint32_t smem_u32(const void* p) {
    uint32_t a;
    asm("{ .reg .u64 t; cvta.to.shared.u64 t, %1; cvt.u32.u64 %0, t; }" : "=r"(a) : "l"(p));
    return a;
}
__device__ __forceinline__ void ldsm4(uint32_t& r0, uint32_t& r1, uint32_t& r2, uint32_t& r3, uint32_t addr) {
    asm volatile("ldmatrix.sync.aligned.m8n8.x4.shared.b16 {%0,%1,%2,%3}, [%4];"
        : "=r"(r0), "=r"(r1), "=r"(r2), "=r"(r3) : "r"(addr));
}
__device__ __forceinline__ void mma16816(float* d, const uint32_t* a, uint32_t b0, uint32_t b1) {
    asm volatile("mma.sync.aligned.m16n8k16.row.col.f32.bf16.bf16.f32 "
        "{%0,%1,%2,%3}, {%4,%5,%6,%7}, {%8,%9}, {%0,%1,%2,%3};"
        : "+f"(d[0]), "+f"(d[1]), "+f"(d[2]), "+f"(d[3])
        : "r"(a[0]), "r"(a[1]), "r"(a[2]), "r"(a[3]), "r"(b0), "r"(b1));
}
#define CP16(dst, src) asm volatile("cp.async.cg.shared.global [%0], [%1], 16;" :: "r"(dst), "l"(src))
#define CP_COMMIT()    asm volatile("cp.async.commit_group;" ::: "memory")
#define CP_WAIT1()     asm volatile("cp.async.wait_group 1;" ::: "memory")

__device__ __forceinline__ float gelu_exact(float v) {
    return 0.5f * v * (1.0f + erff(v * 0.70710678118654752f));
}
__device__ __forceinline__ uint32_t pack_hi2(float a, float b) {
    return __byte_perm(__float_as_uint(a), __float_as_uint(b), 0x7632);
}
__device__ __forceinline__ uint32_t pack_lo2(float a, float b) {
    float ra = a - __uint_as_float(__float_as_uint(a) & 0xffff0000u);
    float rb = b - __uint_as_float(__float_as_uint(b) & 0xffff0000u);
    __nv_bfloat162 p = __floats2bfloat162_rn(ra, rb);
    return *reinterpret_cast<uint32_t*>(&p);
}
__device__ __forceinline__ void decode_tile(int t, int& b, int& y, int& x0) {
    b = t >> 9;
    int r = t & 511;
    int j = r >> 1;
    x0 = (r & 1) << 7;
    if (j == 0) y = 0;
    else if (j == 1) y = 128;
    else { int tt = j >> 1; y = (j & 1) ? (256 - tt) : tt; }
}

// ---------------------------------------------------------------------------
// SMEM: B hi 32KB | B lo 32KB | A 3 stages x 16KB (k32 chunks)
// A stage layout: hi 8KB (128 rows x 64B) + lo 8KB; swizzle c16 ^= (row>>1)&3
// ---------------------------------------------------------------------------
#define SM_BHI  0u
#define SM_BLO  32768u
#define SM_AST  65536u
#define SM_DYN  114688

// ---------------------------------------------------------------------------
// Weight prep (combined weights -> bf16 hi/lo, swizzled smem image, SW128)
// ---------------------------------------------------------------------------
__global__ void prep_w_kernel(const float* __restrict__ wr,
                              const float* __restrict__ wi,
                              const float* __restrict__ cw,
                              unsigned short* __restrict__ whi,
                              unsigned short* __restrict__ wlo)
{
    int idx = blockIdx.x * blockDim.x + threadIdx.x;   // < 131072
    int l = idx >> 15;
    int rem = idx & 32767;
    int kc = rem >> 13;
    int rem2 = rem & 8191;
    int o = rem2 >> 6;
    int kl = rem2 & 63;
    int kg = kc * 64 + kl;
    const float* wrl = wr + (size_t)l * 16384;
    const float* wil = wi + (size_t)l * 16384;
    float v;
    if (kg < 128)
        v = cw[(size_t)l * 16384 + o * 128 + kg] + 0.5f * (wrl[kg * 128 + o] + wil[kg * 128 + o]);
    else {
        int i = kg - 128;
        v = 0.5f * (wrl[i * 128 + o] - wil[i * 128 + o]);
    }
    uint32_t u = __float_as_uint(v);
    float hf = __uint_as_float(u & 0xffff0000u);
    float lo = v - hf;
    uint32_t off = (uint32_t)o * 128 + kl * 2;
    off ^= (off >> 3) & 0x70;
    size_t cbase = (size_t)(l * 4 + kc) * 8192;
    whi[cbase + (off >> 1)] = (unsigned short)(u >> 16);
    __nv_bfloat16 lb = __float2bfloat16_rn(lo);
    wlo[cbase + (off >> 1)] = __bfloat16_as_ushort(lb);
}

// Closed-form Dirichlet: s(x) = -(1/128) * sum_{k=1}^{127} sin(pi*k*x/128)
__global__ void prep_sx_kernel(float* __restrict__ sx)
{
    int x = threadIdx.x;
    double s = 0.0;
    if (x) {
        double th = M_PI * (double)x / 128.0;
        s = sin(63.5 * th) * sin(64.0 * th) / sin(0.5 * th);
    }
    sx[x] = (float)(-s / 128.0);
}

// ---------------------------------------------------------------------------
// Input transform -> bf16 hi/lo buffers
// ---------------------------------------------------------------------------
__global__ void in_kernel(const float* __restrict__ x,
                          const float* __restrict__ w,
                          const float* __restrict__ bias,
                          unsigned short* __restrict__ oh,
                          unsigned short* __restrict__ ol)
{
    int gid = blockIdx.x * blockDim.x + threadIdx.x;
    int pix = gid >> 5;
    int c4 = (gid & 31) << 2;
    int b = pix >> 16;
    int yx = pix & 65535;
    const float* xb = x + (size_t)b * 196608 + yx;
    float x0 = __ldg(xb);
    float x1 = __ldg(xb + 65536);
    float x2 = __ldg(xb + 131072);
    float4 w0 = __ldg((const float4*)(w + c4));
    float4 w1 = __ldg((const float4*)(w + 128 + c4));
    float4 w2 = __ldg((const float4*)(w + 256 + c4));
    float4 bb = __ldg((const float4*)(bias + c4));
    float4 o;
    o.x = gelu_exact(x0 * w0.x + x1 * w1.x + x2 * w2.x + bb.x);
    o.y = gelu_exact(x0 * w0.y + x1 * w1.y + x2 * w2.y + bb.y);
    o.z = gelu_exact(x0 * w0.z + x1 * w1.z + x2 * w2.z + bb.z);
    o.w = gelu_exact(x0 * w0.w + x1 * w1.w + x2 * w2.w + bb.w);
    uint2 hv, lv;
    hv.x = pack_hi2(o.x, o.y); hv.y = pack_hi2(o.z, o.w);
    lv.x = pack_lo2(o.x, o.y); lv.y = pack_lo2(o.z, o.w);
    *(uint2*)((uint32_t*)oh + (size_t)pix * 64 + (c4 >> 1)) = hv;
    *(uint2*)((uint32_t*)ol + (size_t)pix * 64 + (c4 >> 1)) = lv;
}

// Final gelu over the two n-half partials
__global__ void out_finish(const float* __restrict__ part,
                           const float* __restrict__ lob,
                           float* __restrict__ out)
{
    int p = blockIdx.x * blockDim.x + threadIdx.x;
    out[p] = gelu_exact(part[p] + part[NPIX + p] + __ldg(lob));
}

// ---------------------------------------------------------------------------
// Layer kernel: 2 CTAs/SM, each owns a 64-col n-half; cp.async 3-stage A
// ---------------------------------------------------------------------------
__global__ void __launch_bounds__(THREADS, 2) layer_kernel(
    const unsigned short* __restrict__ hH, const unsigned short* __restrict__ hL,
    unsigned short* __restrict__ oH, unsigned short* __restrict__ oL,
    const uint4* __restrict__ whiL, const uint4* __restrict__ wloL,
    const float* __restrict__ cbp, const float* __restrict__ brp,
    const float* __restrict__ bip, const float* __restrict__ lowp,
    float* __restrict__ pout, int fuse)
{
    extern __shared__ char dsm_raw[];
    uint32_t raw = smem_u32(dsm_raw);
    uint32_t sbase = (raw + 127) & ~127u;
    char* sm = dsm_raw + (sbase - raw);

    int tid = threadIdx.x;
    int wid = tid >> 5;
    int lane = tid & 31;
    int bid2 = blockIdx.x >> 1;      // tile stream id (0..151)
    int nh = blockIdx.x & 1;         // n-half owned by this CTA
    int wm = wid & 3;                // 4 m-groups x 32 rows
    int wn = wid >> 2;               // 2 n-groups x 32 cols (within half)

    // cp.async mapping: 2 threads per pixel row, 32B (2x16B) each
    int m = tid >> 1;
    int q = tid & 1;
    uint32_t asw = (uint32_t)((m >> 1) & 3);
    uint32_t off0 = (uint32_t)m * 64u + ((((uint32_t)q * 2u) ^ asw) << 4);
    uint32_t off1 = (uint32_t)m * 64u + ((((uint32_t)q * 2u + 1u) ^ asw) << 4);

    int nloc = (NTILES - bid2 + 151) / 152;
    int totalC = nloc * 8;

    auto issue_chunk = [&](int cc) {
        if (cc < totalC) {
            int i2 = cc >> 3, c = cc & 7;
            int t = bid2 + i2 * 152;
            int b, y, x0;
            decode_tile(t, b, y, x0);
            size_t pix;
            int koff;
            if (c < 4) {
                pix = ((size_t)(b * 256 + y)) * 256 + x0 + m;
                koff = c * 32 + q * 16;
            } else {
                int yf = (256 - y) & 255;
                int xf = (256 - (x0 + m)) & 255;
                pix = ((size_t)(b * 256 + yf)) * 256 + xf;
                koff = (c - 4) * 32 + q * 16;
            }
            const unsigned short* sH = hH + pix * 128 + koff;
            const unsigned short* sL = hL + pix * 128 + koff;
            uint32_t stb = sbase + SM_AST + (uint32_t)(cc % 3) * 16384u;
            CP16(stb + off0, sH);
            CP16(stb + off1, sH + 8);
            CP16(stb + 8192u + off0, sL);
            CP16(stb + 8192u + off1, sL + 8);
        }
        CP_COMMIT();
    };

    // prologue: issue first two chunks, then load this n-half of B
    issue_chunk(0);
    issue_chunk(1);
    {
        uint4* bh = (uint4*)(sm + SM_BHI);
        uint4* bl = (uint4*)(sm + SM_BLO);
        #pragma unroll
        for (int qq = 0; qq < 8; qq++) {
            int i = tid + qq * 256;
            int kc = i >> 9, j = i & 511;
            bh[i] = __ldg(whiL + kc * 1024 + nh * 512 + j);
            bl[i] = __ldg(wloL + kc * 1024 + nh * 512 + j);
        }
    }
    __syncthreads();

    // ldsm per-lane address components
    int grp = lane >> 3, lr = lane & 7;
    // A (64B rows): row = wm*32 + mt*16 + lr + (grp&1)*8 ; c16 += (grp>>1)
    uint32_t a_c16k = (uint32_t)(grp >> 1);
    uint32_t arowb[2], asel[2];
    #pragma unroll
    for (int mt = 0; mt < 2; mt++) {
        uint32_t row = (uint32_t)(wm * 32 + mt * 16 + lr + ((grp & 1) << 3));
        arowb[mt] = row * 64u;
        asel[mt] = (row >> 1) & 3u;
    }
    // B (128B rows, SW128): row = wn*32 + np*16 + lr + (grp>>1)*8
    uint32_t xm = (uint32_t)(lr << 4);
    uint32_t b_c16 = (uint32_t)((grp & 1) << 4);
    uint32_t brow[2];
    #pragma unroll
    for (int np = 0; np < 2; np++)
        brow[np] = (uint32_t)(wn * 32 + np * 16 + lr + ((grp >> 1) << 3)) * 128u;

    // hoisted biases for this thread's n columns
    float cbv[8], lwv[8];
    #pragma unroll
    for (int nt = 0; nt < 4; nt++) {
        int n = nh * 64 + wn * 32 + nt * 8 + (lane & 3) * 2;
        cbv[nt * 2]     = __ldg(cbp + n);
        cbv[nt * 2 + 1] = __ldg(cbp + n + 1);
        if (fuse) {
            lwv[nt * 2]     = __ldg(lowp + n);
            lwv[nt * 2 + 1] = __ldg(lowp + n + 1);
        }
    }

    float acc[2][4][4];

    for (int cc = 0; cc < totalC; cc++) {
        int c = cc & 7;
        int st = cc % 3;
        CP_WAIT1();
        __syncthreads();
        issue_chunk(cc + 2);

        if (c == 0) {
            #pragma unroll
            for (int mt = 0; mt < 2; mt++)
                #pragma unroll
                for (int nt = 0; nt < 4; nt++)
                    #pragma unroll
                    for (int z = 0; z < 4; z++) acc[mt][nt][z] = 0.0f;
        }

        uint32_t aBase = sbase + SM_AST + (uint32_t)st * 16384u;
        uint32_t bHi = sbase + SM_BHI + (uint32_t)(c >> 1) * 8192u;
        uint32_t bLo = sbase + SM_BLO + (uint32_t)(c >> 1) * 8192u;
        int ks0 = (c & 1) * 2;

        #pragma unroll
        for (int ks = 0; ks < 2; ks++) {
            uint32_t c16 = (uint32_t)(ks * 2) + a_c16k;
            uint32_t ah[2][4], al[2][4];
            #pragma unroll
            for (int mt = 0; mt < 2; mt++) {
                uint32_t aoff = arowb[mt] + ((c16 ^ asel[mt]) << 4);
                ldsm4(ah[mt][0], ah[mt][1], ah[mt][2], ah[mt][3], aBase + aoff);
                ldsm4(al[mt][0], al[mt][1], al[mt][2], al[mt][3], aBase + 8192u + aoff);
            }
            uint32_t bcb = (((uint32_t)(ks0 + ks) * 32u) + b_c16) ^ xm;
            #pragma unroll
            for (int np = 0; np < 2; np++) {
                uint32_t bh[4], bl[4];
                ldsm4(bh[0], bh[1], bh[2], bh[3], bHi + brow[np] + bcb);
                ldsm4(bl[0], bl[1], bl[2], bl[3], bLo + brow[np] + bcb);
                #pragma unroll
                for (int mt = 0; mt < 2; mt++) {
                    mma16816(acc[mt][np * 2],     ah[mt], bh[0], bh[1]);
                    mma16816(acc[mt][np * 2 + 1], ah[mt], bh[2], bh[3]);
                    mma16816(acc[mt][np * 2],     ah[mt], bl[0], bl[1]);
                    mma16816(acc[mt][np * 2 + 1], ah[mt], bl[2], bl[3]);
                    mma16816(acc[mt][np * 2],     al[mt], bh[0], bh[1]);
                    mma16816(acc[mt][np * 2 + 1], al[mt], bh[2], bh[3]);
                }
            }
        }

        if (c == 7) {
            // ---- epilogue for tile (cc>>3) ----
            int t = bid2 + (cc >> 3) * 152;
            int b, y, x0;
            decode_tile(t, b, y, x0);
            size_t base = ((size_t)(b * 256 + y)) * 256 + x0;
            bool row0 = (y == 0);

            if (!fuse) {
                #pragma unroll
                for (int mt = 0; mt < 2; mt++) {
                    #pragma unroll
                    for (int rh = 0; rh < 2; rh++) {
                        int mm = wm * 32 + mt * 16 + (lane >> 2) + rh * 8;
                        int xx = x0 + mm;
                        float sxv = row0 ? __ldg(&g_sx[xx]) : 0.0f;
                        size_t pix = base + mm;
                        uint32_t* rowH = (uint32_t*)oH + pix * 64;
                        uint32_t* rowL = (uint32_t*)oL + pix * 64;
                        #pragma unroll
                        for (int nt = 0; nt < 4; nt++) {
                            int n = nh * 64 + wn * 32 + nt * 8 + (lane & 3) * 2;
                            float v0 = acc[mt][nt][rh * 2]     + cbv[nt * 2];
                            float v1 = acc[mt][nt][rh * 2 + 1] + cbv[nt * 2 + 1];
                            if (row0) {
                                v0 += __ldg(bip + n) * sxv;
                                v1 += __ldg(bip + n + 1) * sxv;
                                if (xx == 0) { v0 += __ldg(brp + n); v1 += __ldg(brp + n + 1); }
                            }
                            float g0 = gelu_exact(v0);
                            float g1 = gelu_exact(v1);
                            rowH[n >> 1] = pack_hi2(g0, g1);
                            rowL[n >> 1] = pack_lo2(g0, g1);
                        }
                    }
                }
            } else {
                // fused final layer: partial over this n-half
                float part[2][2];
                #pragma unroll
                for (int mt = 0; mt < 2; mt++) {
                    #pragma unroll
                    for (int rh = 0; rh < 2; rh++) {
                        int mm = wm * 32 + mt * 16 + (lane >> 2) + rh * 8;
                        int xx = x0 + mm;
                        float sxv = row0 ? __ldg(&g_sx[xx]) : 0.0f;
                        float p = 0.0f;
                        #pragma unroll
                        for (int nt = 0; nt < 4; nt++) {
                            int n = nh * 64 + wn * 32 + nt * 8 + (lane & 3) * 2;
                            float v0 = acc[mt][nt][rh * 2]     + cbv[nt * 2];
                            float v1 = acc[mt][nt][rh * 2 + 1] + cbv[nt * 2 + 1];
                            if (row0) {
                                v0 += __ldg(bip + n) * sxv;
                                v1 += __ldg(bip + n + 1) * sxv;
                                if (xx == 0) { v0 += __ldg(brp + n); v1 += __ldg(brp + n + 1); }
                            }
                            p += gelu_exact(v0) * lwv[nt * 2]
                               + gelu_exact(v1) * lwv[nt * 2 + 1];
                        }
                        p += __shfl_xor_sync(0xffffffffu, p, 1);
                        p += __shfl_xor_sync(0xffffffffu, p, 2);
                        part[mt][rh] = p;
                    }
                }
                // red scratch aliases the just-consumed A stage (barrier first)
                float* red = (float*)(sm + SM_AST + (uint32_t)st * 16384u);
                __syncthreads();   // all warps done reading stage st
                if ((lane & 3) == 0) {
                    #pragma unroll
                    for (int mt = 0; mt < 2; mt++)
                        #pragma unroll
                        for (int rh = 0; rh < 2; rh++) {
                            int mm = wm * 32 + mt * 16 + (lane >> 2) + rh * 8;
                            red[wn * 128 + mm] = part[mt][rh];
                        }
                }
                __syncthreads();
                if (tid < 128)
                    pout[(size_t)nh * NPIX + base + tid] = red[tid] + red[128 + tid];
            }
        }
    }
}

// ---------------------------------------------------------------------------
extern "C" void kernel_launch(void* const* d_in, const int* in_sizes, int n_in,
                              void* d_out, int out_size)
{
    const float* x   = (const float*)d_in[0];
    const float* liw = (const float*)d_in[1];
    const float* lib = (const float*)d_in[2];
    const float* wr  = (const float*)d_in[3];
    const float* wi  = (const float*)d_in[4];
    const float* br  = (const float*)d_in[5];
    const float* bi  = (const float*)d_in[6];
    const float* cw  = (const float*)d_in[7];
    const float* cb  = (const float*)d_in[8];
    const float* low = (const float*)d_in[9];
    const float* lob = (const float*)d_in[10];
    float* out = (float*)d_out;

    unsigned short *h0, *l0, *h1, *l1, *whi, *wlo;
    float* sx;
    cudaGetSymbolAddress((void**)&h0, g_h0);
    cudaGetSymbolAddress((void**)&l0, g_l0);
    cudaGetSymbolAddress((void**)&h1, g_h1);
    cudaGetSymbolAddress((void**)&l1, g_l1);
    cudaGetSymbolAddress((void**)&whi, g_whi);
    cudaGetSymbolAddress((void**)&wlo, g_wlo);
    cudaGetSymbolAddress((void**)&sx, g_sx);

    cudaFuncSetAttribute(layer_kernel, cudaFuncAttributeMaxDynamicSharedMemorySize, SM_DYN);

    prep_w_kernel<<<512, 256>>>(wr, wi, cw, whi, wlo);
    prep_sx_kernel<<<1, 256>>>(sx);
    in_kernel<<<NPIX * 32 / 256, 256>>>(x, liw, lib, h0, l0);

    unsigned short* hs[2] = { h0, h1 };
    unsigned short* ls[2] = { l0, l1 };
    float* pbuf = (float*)h0;   // final-layer partial scratch (reuses h0)
    for (int l = 0; l < NL; l++) {
        int fuse = (l == NL - 1) ? 1 : 0;
        layer_kernel<<<GRID, THREADS, SM_DYN>>>(
            hs[l & 1], ls[l & 1], hs[(l & 1) ^ 1], ls[(l & 1) ^ 1],
            (const uint4*)(whi + (size_t)l * 4 * 8192),
            (const uint4*)(wlo + (size_t)l * 4 * 8192),
            cb + l * HID, br + l * HID, bi + l * HID,
            low, pbuf, fuse);
    }
    out_finish<<<NPIX / 256, 256>>>(pbuf, lob, out);
}

// round 8
// speedup vs baseline: 1.1454x; 1.1454x over previous
#include <cuda_runtime.h>
#include <cuda_bf16.h>
#include <math.h>
#include <stdint.h>

#define HID 128
#define NPIX (4*256*256)
#define NL 4
#define NTILES 2048
#define GRID 152

// ---------------------------------------------------------------------------
// Device globals: activations as bf16 hi/lo pairs (exact fp32 split)
// ---------------------------------------------------------------------------
__device__ unsigned short g_h0[(size_t)NPIX * HID];
__device__ unsigned short g_l0[(size_t)NPIX * HID];
__device__ unsigned short g_h1[(size_t)NPIX * HID];
__device__ unsigned short g_l1[(size_t)NPIX * HID];
__device__ unsigned short g_whi[NL * 4 * 8192];
__device__ unsigned short g_wlo[NL * 4 * 8192];
__device__ float g_sx[256];

// ---------------------------------------------------------------------------
// Helpers
// ---------------------------------------------------------------------------
__device__ __forceinline__ uint32_t smem_u32(const void* p) {
    uint32_t a;
    asm("{ .reg .u64 t; cvta.to.shared.u64 t, %1; cvt.u32.u64 %0, t; }" : "=r"(a) : "l"(p));
    return a;
}
__device__ __forceinline__ void ldsm4(uint32_t& r0, uint32_t& r1, uint32_t& r2, uint32_t& r3, uint32_t addr) {
    asm volatile("ldmatrix.sync.aligned.m8n8.x4.shared.b16 {%0,%1,%2,%3}, [%4];"
        : "=r"(r0), "=r"(r1), "=r"(r2), "=r"(r3) : "r"(addr));
}
__device__ __forceinline__ void mma16816(float* d, const uint32_t* a, uint32_t b0, uint32_t b1) {
    asm volatile("mma.sync.aligned.m16n8k16.row.col.f32.bf16.bf16.f32 "
        "{%0,%1,%2,%3}, {%4,%5,%6,%7}, {%8,%9}, {%0,%1,%2,%3};"
        : "+f"(d[0]), "+f"(d[1]), "+f"(d[2]), "+f"(d[3])
        : "r"(a[0]), "r"(a[1]), "r"(a[2]), "r"(a[3]), "r"(b0), "r"(b1));
}
#define CP16(dst, src) asm volatile("cp.async.cg.shared.global [%0], [%1], 16;" :: "r"(dst), "l"(src))
#define CP_COMMIT()    asm volatile("cp.async.commit_group;" ::: "memory")
#define CP_WAIT1()     asm volatile("cp.async.wait_group 1;" ::: "memory")

__device__ __forceinline__ float gelu_exact(float v) {
    return 0.5f * v * (1.0f + erff(v * 0.70710678118654752f));
}
__device__ __forceinline__ uint32_t pack_hi2(float a, float b) {
    return __byte_perm(__float_as_uint(a), __float_as_uint(b), 0x7632);
}
__device__ __forceinline__ uint32_t pack_lo2(float a, float b) {
    float ra = a - __uint_as_float(__float_as_uint(a) & 0xffff0000u);
    float rb = b - __uint_as_float(__float_as_uint(b) & 0xffff0000u);
    __nv_bfloat162 p = __floats2bfloat162_rn(ra, rb);
    return *reinterpret_cast<uint32_t*>(&p);
}
__device__ __forceinline__ void decode_tile(int t, int& b, int& y, int& x0) {
    b = t >> 9;
    int r = t & 511;
    int j = r >> 1;
    x0 = (r & 1) << 7;
    if (j == 0) y = 0;
    else if (j == 1) y = 128;
    else { int tt = j >> 1; y = (j & 1) ? (256 - tt) : tt; }
}

// ---------------------------------------------------------------------------
// SMEM layout: A 3 stages x 32KB | B hi 64KB | B lo 64KB | red 2KB
// ---------------------------------------------------------------------------
#define SM_BHI  98304u
#define SM_BLO  163840u
#define SM_RED  229376u
#define SM_DYN  231424

// ---------------------------------------------------------------------------
// Weight prep (combined weights -> bf16 hi/lo, swizzled smem image)
// ---------------------------------------------------------------------------
__global__ void prep_w_kernel(const float* __restrict__ wr,
                              const float* __restrict__ wi,
                              const float* __restrict__ cw,
                              unsigned short* __restrict__ whi,
                              unsigned short* __restrict__ wlo)
{
    int idx = blockIdx.x * blockDim.x + threadIdx.x;   // < 131072
    int l = idx >> 15;
    int rem = idx & 32767;
    int kc = rem >> 13;
    int rem2 = rem & 8191;
    int o = rem2 >> 6;
    int kl = rem2 & 63;
    int kg = kc * 64 + kl;
    const float* wrl = wr + (size_t)l * 16384;
    const float* wil = wi + (size_t)l * 16384;
    float v;
    if (kg < 128)
        v = cw[(size_t)l * 16384 + o * 128 + kg] + 0.5f * (wrl[kg * 128 + o] + wil[kg * 128 + o]);
    else {
        int i = kg - 128;
        v = 0.5f * (wrl[i * 128 + o] - wil[i * 128 + o]);
    }
    uint32_t u = __float_as_uint(v);
    float hf = __uint_as_float(u & 0xffff0000u);
    float lo = v - hf;
    uint32_t off = (uint32_t)o * 128 + kl * 2;
    off ^= (off >> 3) & 0x70;
    size_t cbase = (size_t)(l * 4 + kc) * 8192;
    whi[cbase + (off >> 1)] = (unsigned short)(u >> 16);
    __nv_bfloat16 lb = __float2bfloat16_rn(lo);
    wlo[cbase + (off >> 1)] = __bfloat16_as_ushort(lb);
}

// Closed-form Dirichlet: s(x) = -(1/128) * sum_{k=1}^{127} sin(pi*k*x/128)
__global__ void prep_sx_kernel(float* __restrict__ sx)
{
    int x = threadIdx.x;
    double s = 0.0;
    if (x) {
        double th = M_PI * (double)x / 128.0;
        s = sin(63.5 * th) * sin(64.0 * th) / sin(0.5 * th);
    }
    sx[x] = (float)(-s / 128.0);
}

// ---------------------------------------------------------------------------
// Input transform -> bf16 hi/lo buffers
// ---------------------------------------------------------------------------
__global__ void in_kernel(const float* __restrict__ x,
                          const float* __restrict__ w,
                          const float* __restrict__ bias,
                          unsigned short* __restrict__ oh,
                          unsigned short* __restrict__ ol)
{
    int gid = blockIdx.x * blockDim.x + threadIdx.x;
    int pix = gid >> 5;
    int c4 = (gid & 31) << 2;
    int b = pix >> 16;
    int yx = pix & 65535;
    const float* xb = x + (size_t)b * 196608 + yx;
    float x0 = __ldg(xb);
    float x1 = __ldg(xb + 65536);
    float x2 = __ldg(xb + 131072);
    float4 w0 = __ldg((const float4*)(w + c4));
    float4 w1 = __ldg((const float4*)(w + 128 + c4));
    float4 w2 = __ldg((const float4*)(w + 256 + c4));
    float4 bb = __ldg((const float4*)(bias + c4));
    float4 o;
    o.x = gelu_exact(x0 * w0.x + x1 * w1.x + x2 * w2.x + bb.x);
    o.y = gelu_exact(x0 * w0.y + x1 * w1.y + x2 * w2.y + bb.y);
    o.z = gelu_exact(x0 * w0.z + x1 * w1.z + x2 * w2.z + bb.z);
    o.w = gelu_exact(x0 * w0.w + x1 * w1.w + x2 * w2.w + bb.w);
    uint2 hv, lv;
    hv.x = pack_hi2(o.x, o.y); hv.y = pack_hi2(o.z, o.w);
    lv.x = pack_lo2(o.x, o.y); lv.y = pack_lo2(o.z, o.w);
    *(uint2*)((uint32_t*)oh + (size_t)pix * 64 + (c4 >> 1)) = hv;
    *(uint2*)((uint32_t*)ol + (size_t)pix * 64 + (c4 >> 1)) = lv;
}

// ---------------------------------------------------------------------------
// Layer kernel: persistent, cp.async 3-stage pipeline, RAW-distance-8 MMA order
// ---------------------------------------------------------------------------
__global__ void __launch_bounds__(512, 1) layer_kernel(
    const unsigned short* __restrict__ hH, const unsigned short* __restrict__ hL,
    unsigned short* __restrict__ oH, unsigned short* __restrict__ oL,
    const uint4* __restrict__ whiL, const uint4* __restrict__ wloL,
    const float* __restrict__ cbp, const float* __restrict__ brp,
    const float* __restrict__ bip, const float* __restrict__ lowp,
    const float* __restrict__ lobp, float* __restrict__ gout, int fuse)
{
    extern __shared__ char dsm_raw[];
    uint32_t raw = smem_u32(dsm_raw);
    uint32_t sbase = (raw + 127) & ~127u;
    char* sm = dsm_raw + (sbase - raw);

    int tid = threadIdx.x;
    int wid = tid >> 5;
    int lane = tid & 31;
    int wm = wid & 3;        // 4 m-groups x 32 rows
    int wn = wid >> 2;       // 4 n-groups x 32 cols

    // cp.async mapping: m = tid>>2 pixel row, q = tid&3 (16 k each)
    int m = tid >> 2;
    int q = tid & 3;
    uint32_t swz = (uint32_t)(m & 7) << 4;
    uint32_t off0 = (uint32_t)m * 128u + (((uint32_t)q * 32u) ^ swz);
    uint32_t off1 = (uint32_t)m * 128u + (((uint32_t)q * 32u + 16u) ^ swz);

    int nloc = (NTILES - blockIdx.x + GRID - 1) / GRID;
    int totalC = nloc * 4;

    auto issue_chunk = [&](int cc) {
        if (cc < totalC) {
            int i2 = cc >> 2, kc = cc & 3;
            int t = blockIdx.x + i2 * GRID;
            int b, y, x0;
            decode_tile(t, b, y, x0);
            size_t pix;
            if (kc < 2) {
                pix = ((size_t)(b * 256 + y)) * 256 + x0 + m;
            } else {
                int yf = (256 - y) & 255;
                int xf = (256 - (x0 + m)) & 255;
                pix = ((size_t)(b * 256 + yf)) * 256 + xf;
            }
            int kc2 = kc & 1;
            const unsigned short* sH = hH + pix * 128 + kc2 * 64 + q * 16;
            const unsigned short* sL = hL + pix * 128 + kc2 * 64 + q * 16;
            uint32_t stb = sbase + (uint32_t)(cc % 3) * 32768u;
            CP16(stb + off0, sH);
            CP16(stb + off1, sH + 8);
            CP16(stb + 16384u + off0, sL);
            CP16(stb + 16384u + off1, sL + 8);
        }
        CP_COMMIT();
    };

    // prologue: issue first two chunks, then load B while they fly
    issue_chunk(0);
    issue_chunk(1);
    {
        uint4* bh = (uint4*)(sm + SM_BHI);
        uint4* bl = (uint4*)(sm + SM_BLO);
        #pragma unroll
        for (int qq = 0; qq < 8; qq++) {
            bh[tid + qq * 512] = __ldg(whiL + tid + qq * 512);
            bl[tid + qq * 512] = __ldg(wloL + tid + qq * 512);
        }
    }
    __syncthreads();

    // ldmatrix per-lane address components
    int grp = lane >> 3, lr = lane & 7;
    uint32_t xm = (uint32_t)(lr << 4);
    uint32_t a_rowadd = (uint32_t)(lr + ((grp & 1) << 3));
    uint32_t a_c16 = (uint32_t)((grp >> 1) << 4);
    uint32_t b_rowadd = (uint32_t)(lr + ((grp >> 1) << 3));
    uint32_t b_c16 = (uint32_t)((grp & 1) << 4);
    uint32_t arow[2], brow[2];
    #pragma unroll
    for (int mt = 0; mt < 2; mt++) arow[mt] = (uint32_t)(wm * 32 + mt * 16 + a_rowadd) * 128u;
    #pragma unroll
    for (int np = 0; np < 2; np++) brow[np] = (uint32_t)(wn * 32 + np * 16 + b_rowadd) * 128u;

    // hoisted per-thread bias values (n indices fixed)
    float cbv[8];
    #pragma unroll
    for (int nt = 0; nt < 4; nt++) {
        int n = wn * 32 + nt * 8 + (lane & 3) * 2;
        cbv[nt * 2]     = __ldg(cbp + n);
        cbv[nt * 2 + 1] = __ldg(cbp + n + 1);
    }
    float* red = (float*)(sm + SM_RED);

    float acc[2][4][4];

    for (int cc = 0; cc < totalC; cc++) {
        int kc = cc & 3;
        int st = cc % 3;
        CP_WAIT1();
        __syncthreads();
        issue_chunk(cc + 2);

        if (kc == 0) {
            #pragma unroll
            for (int mt = 0; mt < 2; mt++)
                #pragma unroll
                for (int nt = 0; nt < 4; nt++)
                    #pragma unroll
                    for (int z = 0; z < 4; z++) acc[mt][nt][z] = 0.0f;
        }

        // ---- MMA over chunk kc from stage st ----
        uint32_t aHi = sbase + (uint32_t)st * 32768u;
        uint32_t aLo = aHi + 16384u;
        uint32_t bHi = sbase + SM_BHI + (uint32_t)kc * 16384u;
        uint32_t bLo = sbase + SM_BLO + (uint32_t)kc * 16384u;
        #pragma unroll
        for (int ks = 0; ks < 4; ks++) {
            uint32_t acb = ((uint32_t)(ks * 32) + a_c16) ^ xm;
            uint32_t bcb = ((uint32_t)(ks * 32) + b_c16) ^ xm;
            // load ALL fragments for this ks first
            uint32_t ah[2][4], al[2][4], bh[2][4], bl[2][4];
            #pragma unroll
            for (int mt = 0; mt < 2; mt++) {
                ldsm4(ah[mt][0], ah[mt][1], ah[mt][2], ah[mt][3], aHi + arow[mt] + acb);
                ldsm4(al[mt][0], al[mt][1], al[mt][2], al[mt][3], aLo + arow[mt] + acb);
            }
            #pragma unroll
            for (int np = 0; np < 2; np++) {
                ldsm4(bh[np][0], bh[np][1], bh[np][2], bh[np][3], bHi + brow[np] + bcb);
                ldsm4(bl[np][0], bl[np][1], bl[np][2], bl[np][3], bLo + brow[np] + bcb);
            }
            // combo-major emission: 8 distinct acc targets between same-acc reuse
            #pragma unroll
            for (int np = 0; np < 2; np++)
                #pragma unroll
                for (int mt = 0; mt < 2; mt++) {
                    mma16816(acc[mt][np * 2],     ah[mt], bh[np][0], bh[np][1]);
                    mma16816(acc[mt][np * 2 + 1], ah[mt], bh[np][2], bh[np][3]);
                }
            #pragma unroll
            for (int np = 0; np < 2; np++)
                #pragma unroll
                for (int mt = 0; mt < 2; mt++) {
                    mma16816(acc[mt][np * 2],     ah[mt], bl[np][0], bl[np][1]);
                    mma16816(acc[mt][np * 2 + 1], ah[mt], bl[np][2], bl[np][3]);
                }
            #pragma unroll
            for (int np = 0; np < 2; np++)
                #pragma unroll
                for (int mt = 0; mt < 2; mt++) {
                    mma16816(acc[mt][np * 2],     al[mt], bh[np][0], bh[np][1]);
                    mma16816(acc[mt][np * 2 + 1], al[mt], bh[np][2], bh[np][3]);
                }
        }

        if (kc == 3) {
            // ---- epilogue for tile (cc>>2) ----
            int t = blockIdx.x + (cc >> 2) * GRID;
            int b, y, x0;
            decode_tile(t, b, y, x0);
            size_t base = ((size_t)(b * 256 + y)) * 256 + x0;
            bool row0 = (y == 0);

            if (!fuse) {
                #pragma unroll
                for (int mt = 0; mt < 2; mt++) {
                    #pragma unroll
                    for (int rh = 0; rh < 2; rh++) {
                        int mm = wm * 32 + mt * 16 + (lane >> 2) + rh * 8;
                        int xx = x0 + mm;
                        float sxv = row0 ? __ldg(&g_sx[xx]) : 0.0f;
                        size_t pix = base + mm;
                        uint32_t* rowH = (uint32_t*)oH + pix * 64;
                        uint32_t* rowL = (uint32_t*)oL + pix * 64;
                        #pragma unroll
                        for (int nt = 0; nt < 4; nt++) {
                            int n = wn * 32 + nt * 8 + (lane & 3) * 2;
                            float v0 = acc[mt][nt][rh * 2]     + cbv[nt * 2];
                            float v1 = acc[mt][nt][rh * 2 + 1] + cbv[nt * 2 + 1];
                            if (row0) {
                                v0 += __ldg(bip + n) * sxv;
                                v1 += __ldg(bip + n + 1) * sxv;
                                if (xx == 0) { v0 += __ldg(brp + n); v1 += __ldg(brp + n + 1); }
                            }
                            float g0 = gelu_exact(v0);
                            float g1 = gelu_exact(v1);
                            rowH[n >> 1] = pack_hi2(g0, g1);
                            rowL[n >> 1] = pack_lo2(g0, g1);
                        }
                    }
                }
            } else {
                // fused: out[pix] = gelu( sum_n gelu(v_n)*low[n] + lob )
                #pragma unroll
                for (int mt = 0; mt < 2; mt++) {
                    #pragma unroll
                    for (int rh = 0; rh < 2; rh++) {
                        int mm = wm * 32 + mt * 16 + (lane >> 2) + rh * 8;
                        int xx = x0 + mm;
                        float sxv = row0 ? __ldg(&g_sx[xx]) : 0.0f;
                        float p = 0.0f;
                        #pragma unroll
                        for (int nt = 0; nt < 4; nt++) {
                            int n = wn * 32 + nt * 8 + (lane & 3) * 2;
                            float v0 = acc[mt][nt][rh * 2]     + cbv[nt * 2];
                            float v1 = acc[mt][nt][rh * 2 + 1] + cbv[nt * 2 + 1];
                            if (row0) {
                                v0 += __ldg(bip + n) * sxv;
                                v1 += __ldg(bip + n + 1) * sxv;
                                if (xx == 0) { v0 += __ldg(brp + n); v1 += __ldg(brp + n + 1); }
                            }
                            p += gelu_exact(v0) * __ldg(lowp + n)
                               + gelu_exact(v1) * __ldg(lowp + n + 1);
                        }
                        p += __shfl_xor_sync(0xffffffffu, p, 1);
                        p += __shfl_xor_sync(0xffffffffu, p, 2);
                        if ((lane & 3) == 0) red[wn * 128 + mm] = p;
                    }
                }
                __syncthreads();
                if (tid < 128) {
                    float s = red[tid] + red[128 + tid] + red[256 + tid] + red[384 + tid];
                    gout[base + tid] = gelu_exact(s + __ldg(lobp));
                }
            }
        }
    }
}

// ---------------------------------------------------------------------------
extern "C" void kernel_launch(void* const* d_in, const int* in_sizes, int n_in,
                              void* d_out, int out_size)
{
    const float* x   = (const float*)d_in[0];
    const float* liw = (const float*)d_in[1];
    const float* lib = (const float*)d_in[2];
    const float* wr  = (const float*)d_in[3];
    const float* wi  = (const float*)d_in[4];
    const float* br  = (const float*)d_in[5];
    const float* bi  = (const float*)d_in[6];
    const float* cw  = (const float*)d_in[7];
    const float* cb  = (const float*)d_in[8];
    const float* low = (const float*)d_in[9];
    const float* lob = (const float*)d_in[10];
    float* out = (float*)d_out;

    unsigned short *h0, *l0, *h1, *l1, *whi, *wlo;
    float* sx;
    cudaGetSymbolAddress((void**)&h0, g_h0);
    cudaGetSymbolAddress((void**)&l0, g_l0);
    cudaGetSymbolAddress((void**)&h1, g_h1);
    cudaGetSymbolAddress((void**)&l1, g_l1);
    cudaGetSymbolAddress((void**)&whi, g_whi);
    cudaGetSymbolAddress((void**)&wlo, g_wlo);
    cudaGetSymbolAddress((void**)&sx, g_sx);

    cudaFuncSetAttribute(layer_kernel, cudaFuncAttributeMaxDynamicSharedMemorySize, SM_DYN);

    prep_w_kernel<<<512, 256>>>(wr, wi, cw, whi, wlo);
    prep_sx_kernel<<<1, 256>>>(sx);
    in_kernel<<<NPIX * 32 / 256, 256>>>(x, liw, lib, h0, l0);

    unsigned short* hs[2] = { h0, h1 };
    unsigned short* ls[2] = { l0, l1 };
    for (int l = 0; l < NL; l++) {
        int fuse = (l == NL - 1) ? 1 : 0;
        layer_kernel<<<GRID, 512, SM_DYN>>>(
            hs[l & 1], ls[l & 1], hs[(l & 1) ^ 1], ls[(l & 1) ^ 1],
            (const uint4*)(whi + (size_t)l * 4 * 8192),
            (const uint4*)(wlo + (size_t)l * 4 * 8192),
            cb + l * HID, br + l * HID, bi + l * HID,
            low, lob, out, fuse);
    }
}

// round 9
// speedup vs baseline: 1.2123x; 1.0585x over previous
#include <cuda_runtime.h>
#include <cuda_bf16.h>
#include <math.h>
#include <stdint.h>

#define HID 128
#define NPIX (4*256*256)
#define NL 4
#define NTILES 2048
#define GRID 152

// ---------------------------------------------------------------------------
// Device globals: activations as bf16 hi/lo pairs (exact fp32 split)
// ---------------------------------------------------------------------------
__device__ unsigned short g_h0[(size_t)NPIX * HID];
__device__ unsigned short g_l0[(size_t)NPIX * HID];
__device__ unsigned short g_h1[(size_t)NPIX * HID];
__device__ unsigned short g_l1[(size_t)NPIX * HID];
__device__ unsigned short g_whi[NL * 4 * 8192];
__device__ unsigned short g_wlo[NL * 4 * 8192];
__device__ float g_sx[256];

// ---------------------------------------------------------------------------
// Helpers
// ---------------------------------------------------------------------------
__device__ __forceinline__ uint32_t smem_u32(const void* p) {
    uint32_t a;
    asm("{ .reg .u64 t; cvta.to.shared.u64 t, %1; cvt.u32.u64 %0, t; }" : "=r"(a) : "l"(p));
    return a;
}
__device__ __forceinline__ void ldsm4(uint32_t& r0, uint32_t& r1, uint32_t& r2, uint32_t& r3, uint32_t addr) {
    asm volatile("ldmatrix.sync.aligned.m8n8.x4.shared.b16 {%0,%1,%2,%3}, [%4];"
        : "=r"(r0), "=r"(r1), "=r"(r2), "=r"(r3) : "r"(addr));
}
__device__ __forceinline__ void mma16816(float* d, const uint32_t* a, uint32_t b0, uint32_t b1) {
    asm volatile("mma.sync.aligned.m16n8k16.row.col.f32.bf16.bf16.f32 "
        "{%0,%1,%2,%3}, {%4,%5,%6,%7}, {%8,%9}, {%0,%1,%2,%3};"
        : "+f"(d[0]), "+f"(d[1]), "+f"(d[2]), "+f"(d[3])
        : "r"(a[0]), "r"(a[1]), "r"(a[2]), "r"(a[3]), "r"(b0), "r"(b1));
}
#define CP16(dst, src) asm volatile("cp.async.cg.shared.global [%0], [%1], 16;" :: "r"(dst), "l"(src))
#define CP_COMMIT()    asm volatile("cp.async.commit_group;" ::: "memory")
#define CP_WAIT1()     asm volatile("cp.async.wait_group 1;" ::: "memory")

__device__ __forceinline__ float gelu_exact(float v) {
    return 0.5f * v * (1.0f + erff(v * 0.70710678118654752f));
}
__device__ __forceinline__ uint32_t pack_hi2(float a, float b) {
    return __byte_perm(__float_as_uint(a), __float_as_uint(b), 0x7632);
}
__device__ __forceinline__ uint32_t pack_lo2(float a, float b) {
    float ra = a - __uint_as_float(__float_as_uint(a) & 0xffff0000u);
    float rb = b - __uint_as_float(__float_as_uint(b) & 0xffff0000u);
    __nv_bfloat162 p = __floats2bfloat162_rn(ra, rb);
    return *reinterpret_cast<uint32_t*>(&p);
}
__device__ __forceinline__ void decode_tile(int t, int& b, int& y, int& x0) {
    b = t >> 9;
    int r = t & 511;
    int j = r >> 1;
    x0 = (r & 1) << 7;
    if (j == 0) y = 0;
    else if (j == 1) y = 128;
    else { int tt = j >> 1; y = (j & 1) ? (256 - tt) : tt; }
}

// ---------------------------------------------------------------------------
// SMEM layout: A 3 stages x 32KB | B hi 64KB | B lo 64KB | red 2KB
// ---------------------------------------------------------------------------
#define SM_BHI  98304u
#define SM_BLO  163840u
#define SM_RED  229376u
#define SM_DYN  231424

// ---------------------------------------------------------------------------
// Weight prep (combined weights -> bf16 hi/lo, swizzled smem image)
// ---------------------------------------------------------------------------
__global__ void prep_w_kernel(const float* __restrict__ wr,
                              const float* __restrict__ wi,
                              const float* __restrict__ cw,
                              unsigned short* __restrict__ whi,
                              unsigned short* __restrict__ wlo)
{
    int idx = blockIdx.x * blockDim.x + threadIdx.x;   // < 131072
    int l = idx >> 15;
    int rem = idx & 32767;
    int kc = rem >> 13;
    int rem2 = rem & 8191;
    int o = rem2 >> 6;
    int kl = rem2 & 63;
    int kg = kc * 64 + kl;
    const float* wrl = wr + (size_t)l * 16384;
    const float* wil = wi + (size_t)l * 16384;
    float v;
    if (kg < 128)
        v = cw[(size_t)l * 16384 + o * 128 + kg] + 0.5f * (wrl[kg * 128 + o] + wil[kg * 128 + o]);
    else {
        int i = kg - 128;
        v = 0.5f * (wrl[i * 128 + o] - wil[i * 128 + o]);
    }
    uint32_t u = __float_as_uint(v);
    float hf = __uint_as_float(u & 0xffff0000u);
    float lo = v - hf;
    uint32_t off = (uint32_t)o * 128 + kl * 2;
    off ^= (off >> 3) & 0x70;
    size_t cbase = (size_t)(l * 4 + kc) * 8192;
    whi[cbase + (off >> 1)] = (unsigned short)(u >> 16);
    __nv_bfloat16 lb = __float2bfloat16_rn(lo);
    wlo[cbase + (off >> 1)] = __bfloat16_as_ushort(lb);
}

// Closed-form Dirichlet: s(x) = -(1/128) * sum_{k=1}^{127} sin(pi*k*x/128)
__global__ void prep_sx_kernel(float* __restrict__ sx)
{
    int x = threadIdx.x;
    double s = 0.0;
    if (x) {
        double th = M_PI * (double)x / 128.0;
        s = sin(63.5 * th) * sin(64.0 * th) / sin(0.5 * th);
    }
    sx[x] = (float)(-s / 128.0);
}

// ---------------------------------------------------------------------------
// Input transform -> bf16 hi/lo buffers
// ---------------------------------------------------------------------------
__global__ void in_kernel(const float* __restrict__ x,
                          const float* __restrict__ w,
                          const float* __restrict__ bias,
                          unsigned short* __restrict__ oh,
                          unsigned short* __restrict__ ol)
{
    int gid = blockIdx.x * blockDim.x + threadIdx.x;
    int pix = gid >> 5;
    int c4 = (gid & 31) << 2;
    int b = pix >> 16;
    int yx = pix & 65535;
    const float* xb = x + (size_t)b * 196608 + yx;
    float x0 = __ldg(xb);
    float x1 = __ldg(xb + 65536);
    float x2 = __ldg(xb + 131072);
    float4 w0 = __ldg((const float4*)(w + c4));
    float4 w1 = __ldg((const float4*)(w + 128 + c4));
    float4 w2 = __ldg((const float4*)(w + 256 + c4));
    float4 bb = __ldg((const float4*)(bias + c4));
    float4 o;
    o.x = gelu_exact(x0 * w0.x + x1 * w1.x + x2 * w2.x + bb.x);
    o.y = gelu_exact(x0 * w0.y + x1 * w1.y + x2 * w2.y + bb.y);
    o.z = gelu_exact(x0 * w0.z + x1 * w1.z + x2 * w2.z + bb.z);
    o.w = gelu_exact(x0 * w0.w + x1 * w1.w + x2 * w2.w + bb.w);
    uint2 hv, lv;
    hv.x = pack_hi2(o.x, o.y); hv.y = pack_hi2(o.z, o.w);
    lv.x = pack_lo2(o.x, o.y); lv.y = pack_lo2(o.z, o.w);
    *(uint2*)((uint32_t*)oh + (size_t)pix * 64 + (c4 >> 1)) = hv;
    *(uint2*)((uint32_t*)ol + (size_t)pix * 64 + (c4 >> 1)) = lv;
}

// ---------------------------------------------------------------------------
// Layer kernel: persistent, 3-stage cp.async, hoisted per-tile addressing
// ---------------------------------------------------------------------------
__global__ void __launch_bounds__(512, 1) layer_kernel(
    const unsigned short* __restrict__ hH, const unsigned short* __restrict__ hL,
    unsigned short* __restrict__ oH, unsigned short* __restrict__ oL,
    const uint4* __restrict__ whiL, const uint4* __restrict__ wloL,
    const float* __restrict__ cbp, const float* __restrict__ brp,
    const float* __restrict__ bip, const float* __restrict__ lowp,
    const float* __restrict__ lobp, float* __restrict__ gout, int fuse)
{
    extern __shared__ char dsm_raw[];
    uint32_t raw = smem_u32(dsm_raw);
    uint32_t sbase = (raw + 127) & ~127u;
    char* sm = dsm_raw + (sbase - raw);

    int tid = threadIdx.x;
    int wid = tid >> 5;
    int lane = tid & 31;
    int wm = wid & 3;        // 4 m-groups x 32 rows
    int wn = wid >> 2;       // 4 n-groups x 32 cols

    // cp.async mapping: m = tid>>2 pixel row, q = tid&3 (16 k each)
    int m = tid >> 2;
    int q = tid & 3;
    uint32_t swz = (uint32_t)(m & 7) << 4;
    uint32_t off0 = (uint32_t)m * 128u + (((uint32_t)q * 32u) ^ swz);
    uint32_t off1 = (uint32_t)m * 128u + (((uint32_t)q * 32u + 16u) ^ swz);
    uint32_t off0l = off0 + 16384u, off1l = off1 + 16384u;
    int qk = q * 16;

    int nloc = (NTILES - blockIdx.x + GRID - 1) / GRID;

    // per-tile pointer builders (executed once per tile, not per chunk)
    auto ptrD = [&](int t, const unsigned short*& pH, const unsigned short*& pL,
                    size_t& base) {
        int b, y, x0;
        decode_tile(t, b, y, x0);
        base = ((size_t)(b * 256 + y)) * 256 + x0;
        size_t e = (base + m) * 128 + qk;
        pH = hH + e;
        pL = hL + e;
    };
    auto ptrF = [&](int t, const unsigned short*& pH, const unsigned short*& pL) {
        int b, y, x0;
        decode_tile(t, b, y, x0);
        int yf = (256 - y) & 255;
        int xf = (256 - (x0 + m)) & 255;
        size_t e = (((size_t)(b * 256 + yf)) * 256 + xf) * 128 + qk;
        pH = hH + e;
        pL = hL + e;
    };

    uint32_t stIssue = 0;   // stage for next issue
    auto issue = [&](const unsigned short* pH, const unsigned short* pL, int koff) {
        uint32_t stb = sbase + stIssue * 32768u;
        CP16(stb + off0,  pH + koff);
        CP16(stb + off1,  pH + koff + 8);
        CP16(stb + off0l, pL + koff);
        CP16(stb + off1l, pL + koff + 8);
        CP_COMMIT();
        stIssue = (stIssue == 2) ? 0 : stIssue + 1;
    };
    auto issue_empty = [&]() {
        CP_COMMIT();
        stIssue = (stIssue == 2) ? 0 : stIssue + 1;
    };

    // ---- prologue: issue tile0 chunks 0,1; load B while they fly ----
    const unsigned short *pDH, *pDL, *pFH, *pFL, *pD2H, *pD2L;
    size_t baseCur, baseNext;
    ptrD(blockIdx.x, pDH, pDL, baseCur);
    issue(pDH, pDL, 0);
    issue(pDH, pDL, 64);
    {
        uint4* bh = (uint4*)(sm + SM_BHI);
        uint4* bl = (uint4*)(sm + SM_BLO);
        #pragma unroll
        for (int qq = 0; qq < 8; qq++) {
            bh[tid + qq * 512] = __ldg(whiL + tid + qq * 512);
            bl[tid + qq * 512] = __ldg(wloL + tid + qq * 512);
        }
    }
    __syncthreads();

    // ldmatrix per-lane address components
    int grp = lane >> 3, lr = lane & 7;
    uint32_t xm = (uint32_t)(lr << 4);
    uint32_t a_rowadd = (uint32_t)(lr + ((grp & 1) << 3));
    uint32_t a_c16 = (uint32_t)((grp >> 1) << 4);
    uint32_t b_rowadd = (uint32_t)(lr + ((grp >> 1) << 3));
    uint32_t b_c16 = (uint32_t)((grp & 1) << 4);
    uint32_t arow[2], brow[2];
    #pragma unroll
    for (int mt = 0; mt < 2; mt++) arow[mt] = (uint32_t)(wm * 32 + mt * 16 + a_rowadd) * 128u;
    #pragma unroll
    for (int np = 0; np < 2; np++) brow[np] = (uint32_t)(wn * 32 + np * 16 + b_rowadd) * 128u;

    // hoisted per-thread bias values (n indices fixed)
    float cbv[8];
    #pragma unroll
    for (int nt = 0; nt < 4; nt++) {
        int n = wn * 32 + nt * 8 + (lane & 3) * 2;
        cbv[nt * 2]     = __ldg(cbp + n);
        cbv[nt * 2 + 1] = __ldg(cbp + n + 1);
    }
    float* red = (float*)(sm + SM_RED);

    float acc[2][4][4];
    uint32_t stM = 0;   // MMA stage

    for (int i = 0; i < nloc; i++) {
        int t = blockIdx.x + i * GRID;
        // pointers needed this tile: flip(t) for chunks 2,3; direct(t+GRID) for next
        ptrF(t, pFH, pFL);
        bool haveNext = (i + 1 < nloc);
        if (haveNext) ptrD(t + GRID, pD2H, pD2L, baseNext);

        int b, y, x0;
        decode_tile(t, b, y, x0);
        bool row0 = (y == 0);

        #pragma unroll
        for (int mt = 0; mt < 2; mt++)
            #pragma unroll
            for (int nt = 0; nt < 4; nt++)
                #pragma unroll
                for (int z = 0; z < 4; z++) acc[mt][nt][z] = 0.0f;

        #pragma unroll
        for (int kc = 0; kc < 4; kc++) {
            CP_WAIT1();
            __syncthreads();
            // issue chunk cc+2 (constant schedule)
            if (kc == 0)      issue(pFH, pFL, 0);
            else if (kc == 1) issue(pFH, pFL, 64);
            else if (kc == 2) { if (haveNext) issue(pD2H, pD2L, 0); else issue_empty(); }
            else              { if (haveNext) issue(pD2H, pD2L, 64); else issue_empty(); }

            // ---- MMA over chunk kc from stage stM ----
            uint32_t aHi = sbase + stM * 32768u;
            uint32_t aLo = aHi + 16384u;
            uint32_t bHi = sbase + SM_BHI + (uint32_t)kc * 16384u;
            uint32_t bLo = sbase + SM_BLO + (uint32_t)kc * 16384u;
            stM = (stM == 2) ? 0 : stM + 1;

            #pragma unroll
            for (int ks = 0; ks < 4; ks++) {
                uint32_t acb = ((uint32_t)(ks * 32) + a_c16) ^ xm;
                uint32_t bcb = ((uint32_t)(ks * 32) + b_c16) ^ xm;
                uint32_t ah[2][4], al[2][4], bh[2][4], bl[2][4];
                #pragma unroll
                for (int mt = 0; mt < 2; mt++) {
                    ldsm4(ah[mt][0], ah[mt][1], ah[mt][2], ah[mt][3], aHi + arow[mt] + acb);
                    ldsm4(al[mt][0], al[mt][1], al[mt][2], al[mt][3], aLo + arow[mt] + acb);
                }
                #pragma unroll
                for (int np = 0; np < 2; np++) {
                    ldsm4(bh[np][0], bh[np][1], bh[np][2], bh[np][3], bHi + brow[np] + bcb);
                    ldsm4(bl[np][0], bl[np][1], bl[np][2], bl[np][3], bLo + brow[np] + bcb);
                }
                #pragma unroll
                for (int np = 0; np < 2; np++)
                    #pragma unroll
                    for (int mt = 0; mt < 2; mt++) {
                        mma16816(acc[mt][np * 2],     ah[mt], bh[np][0], bh[np][1]);
                        mma16816(acc[mt][np * 2 + 1], ah[mt], bh[np][2], bh[np][3]);
                    }
                #pragma unroll
                for (int np = 0; np < 2; np++)
                    #pragma unroll
                    for (int mt = 0; mt < 2; mt++) {
                        mma16816(acc[mt][np * 2],     ah[mt], bl[np][0], bl[np][1]);
                        mma16816(acc[mt][np * 2 + 1], ah[mt], bl[np][2], bl[np][3]);
                    }
                #pragma unroll
                for (int np = 0; np < 2; np++)
                    #pragma unroll
                    for (int mt = 0; mt < 2; mt++) {
                        mma16816(acc[mt][np * 2],     al[mt], bh[np][0], bh[np][1]);
                        mma16816(acc[mt][np * 2 + 1], al[mt], bh[np][2], bh[np][3]);
                    }
            }
        }

        // ---- epilogue for tile t ----
        if (!fuse) {
            #pragma unroll
            for (int mt = 0; mt < 2; mt++) {
                #pragma unroll
                for (int rh = 0; rh < 2; rh++) {
                    int mm = wm * 32 + mt * 16 + (lane >> 2) + rh * 8;
                    int xx = x0 + mm;
                    float sxv = row0 ? __ldg(&g_sx[xx]) : 0.0f;
                    size_t pix = baseCur + mm;
                    uint32_t* rowH = (uint32_t*)oH + pix * 64;
                    uint32_t* rowL = (uint32_t*)oL + pix * 64;
                    #pragma unroll
                    for (int nt = 0; nt < 4; nt++) {
                        int n = wn * 32 + nt * 8 + (lane & 3) * 2;
                        float v0 = acc[mt][nt][rh * 2]     + cbv[nt * 2];
                        float v1 = acc[mt][nt][rh * 2 + 1] + cbv[nt * 2 + 1];
                        if (row0) {
                            v0 += __ldg(bip + n) * sxv;
                            v1 += __ldg(bip + n + 1) * sxv;
                            if (xx == 0) { v0 += __ldg(brp + n); v1 += __ldg(brp + n + 1); }
                        }
                        float g0 = gelu_exact(v0);
                        float g1 = gelu_exact(v1);
                        rowH[n >> 1] = pack_hi2(g0, g1);
                        rowL[n >> 1] = pack_lo2(g0, g1);
                    }
                }
            }
        } else {
            // fused: out[pix] = gelu( sum_n gelu(v_n)*low[n] + lob )
            #pragma unroll
            for (int mt = 0; mt < 2; mt++) {
                #pragma unroll
                for (int rh = 0; rh < 2; rh++) {
                    int mm = wm * 32 + mt * 16 + (lane >> 2) + rh * 8;
                    int xx = x0 + mm;
                    float sxv = row0 ? __ldg(&g_sx[xx]) : 0.0f;
                    float p = 0.0f;
                    #pragma unroll
                    for (int nt = 0; nt < 4; nt++) {
                        int n = wn * 32 + nt * 8 + (lane & 3) * 2;
                        float v0 = acc[mt][nt][rh * 2]     + cbv[nt * 2];
                        float v1 = acc[mt][nt][rh * 2 + 1] + cbv[nt * 2 + 1];
                        if (row0) {
                            v0 += __ldg(bip + n) * sxv;
                            v1 += __ldg(bip + n + 1) * sxv;
                            if (xx == 0) { v0 += __ldg(brp + n); v1 += __ldg(brp + n + 1); }
                        }
                        p += gelu_exact(v0) * __ldg(lowp + n)
                           + gelu_exact(v1) * __ldg(lowp + n + 1);
                    }
                    p += __shfl_xor_sync(0xffffffffu, p, 1);
                    p += __shfl_xor_sync(0xffffffffu, p, 2);
                    if ((lane & 3) == 0) red[wn * 128 + mm] = p;
                }
            }
            __syncthreads();
            if (tid < 128) {
                float s = red[tid] + red[128 + tid] + red[256 + tid] + red[384 + tid];
                gout[baseCur + tid] = gelu_exact(s + __ldg(lobp));
            }
        }
        baseCur = baseNext;
    }
}

// ---------------------------------------------------------------------------
extern "C" void kernel_launch(void* const* d_in, const int* in_sizes, int n_in,
                              void* d_out, int out_size)
{
    const float* x   = (const float*)d_in[0];
    const float* liw = (const float*)d_in[1];
    const float* lib = (const float*)d_in[2];
    const float* wr  = (const float*)d_in[3];
    const float* wi  = (const float*)d_in[4];
    const float* br  = (const float*)d_in[5];
    const float* bi  = (const float*)d_in[6];
    const float* cw  = (const float*)d_in[7];
    const float* cb  = (const float*)d_in[8];
    const float* low = (const float*)d_in[9];
    const float* lob = (const float*)d_in[10];
    float* out = (float*)d_out;

    unsigned short *h0, *l0, *h1, *l1, *whi, *wlo;
    float* sx;
    cudaGetSymbolAddress((void**)&h0, g_h0);
    cudaGetSymbolAddress((void**)&l0, g_l0);
    cudaGetSymbolAddress((void**)&h1, g_h1);
    cudaGetSymbolAddress((void**)&l1, g_l1);
    cudaGetSymbolAddress((void**)&whi, g_whi);
    cudaGetSymbolAddress((void**)&wlo, g_wlo);
    cudaGetSymbolAddress((void**)&sx, g_sx);

    cudaFuncSetAttribute(layer_kernel, cudaFuncAttributeMaxDynamicSharedMemorySize, SM_DYN);

    prep_w_kernel<<<512, 256>>>(wr, wi, cw, whi, wlo);
    prep_sx_kernel<<<1, 256>>>(sx);
    in_kernel<<<NPIX * 32 / 256, 256>>>(x, liw, lib, h0, l0);

    unsigned short* hs[2] = { h0, h1 };
    unsigned short* ls[2] = { l0, l1 };
    for (int l = 0; l < NL; l++) {
        int fuse = (l == NL - 1) ? 1 : 0;
        layer_kernel<<<GRID, 512, SM_DYN>>>(
            hs[l & 1], ls[l & 1], hs[(l & 1) ^ 1], ls[(l & 1) ^ 1],
            (const uint4*)(whi + (size_t)l * 4 * 8192),
            (const uint4*)(wlo + (size_t)l * 4 * 8192),
            cb + l * HID, br + l * HID, bi + l * HID,
            low, lob, out, fuse);
    }
}

// round 10
// speedup vs baseline: 1.2124x; 1.0000x over previous
#include <cuda_runtime.h>
#include <cuda_bf16.h>
#include <math.h>
#include <stdint.h>

#define HID 128
#define NPIX (4*256*256)
#define NL 4
#define NTILES 2048
#define GRID 152

// ---------------------------------------------------------------------------
// Device globals: activations as bf16 hi/lo pairs (exact fp32 split)
// ---------------------------------------------------------------------------
__device__ unsigned short g_h0[(size_t)NPIX * HID];
__device__ unsigned short g_l0[(size_t)NPIX * HID];
__device__ unsigned short g_h1[(size_t)NPIX * HID];
__device__ unsigned short g_l1[(size_t)NPIX * HID];
__device__ unsigned short g_whi[NL * 4 * 8192];
__device__ unsigned short g_wlo[NL * 4 * 8192];
__device__ float g_sx[256];

// ---------------------------------------------------------------------------
// Helpers
// ---------------------------------------------------------------------------
__device__ __forceinline__ uint32_t smem_u32(const void* p) {
    uint32_t a;
    asm("{ .reg .u64 t; cvta.to.shared.u64 t, %1; cvt.u32.u64 %0, t; }" : "=r"(a) : "l"(p));
    return a;
}
__device__ __forceinline__ void ldsm4(uint32_t& r0, uint32_t& r1, uint32_t& r2, uint32_t& r3, uint32_t addr) {
    asm volatile("ldmatrix.sync.aligned.m8n8.x4.shared.b16 {%0,%1,%2,%3}, [%4];"
        : "=r"(r0), "=r"(r1), "=r"(r2), "=r"(r3) : "r"(addr));
}
__device__ __forceinline__ void mma16816(float* d, const uint32_t* a, uint32_t b0, uint32_t b1) {
    asm volatile("mma.sync.aligned.m16n8k16.row.col.f32.bf16.bf16.f32 "
        "{%0,%1,%2,%3}, {%4,%5,%6,%7}, {%8,%9}, {%0,%1,%2,%3};"
        : "+f"(d[0]), "+f"(d[1]), "+f"(d[2]), "+f"(d[3])
        : "r"(a[0]), "r"(a[1]), "r"(a[2]), "r"(a[3]), "r"(b0), "r"(b1));
}
#define CP16(dst, src) asm volatile("cp.async.cg.shared.global [%0], [%1], 16;" :: "r"(dst), "l"(src))
#define CP_COMMIT()    asm volatile("cp.async.commit_group;" ::: "memory")
#define CP_WAIT1()     asm volatile("cp.async.wait_group 1;" ::: "memory")

__device__ __forceinline__ float gelu_exact(float v) {
    return 0.5f * v * (1.0f + erff(v * 0.70710678118654752f));
}
__device__ __forceinline__ uint32_t pack_hi2(float a, float b) {
    return __byte_perm(__float_as_uint(a), __float_as_uint(b), 0x7632);
}
__device__ __forceinline__ uint32_t pack_lo2(float a, float b) {
    float ra = a - __uint_as_float(__float_as_uint(a) & 0xffff0000u);
    float rb = b - __uint_as_float(__float_as_uint(b) & 0xffff0000u);
    __nv_bfloat162 p = __floats2bfloat162_rn(ra, rb);
    return *reinterpret_cast<uint32_t*>(&p);
}
__device__ __forceinline__ void decode_tile(int t, int& b, int& y, int& x0) {
    b = t >> 9;
    int r = t & 511;
    int j = r >> 1;
    x0 = (r & 1) << 7;
    if (j == 0) y = 0;
    else if (j == 1) y = 128;
    else { int tt = j >> 1; y = (j & 1) ? (256 - tt) : tt; }
}

// ---------------------------------------------------------------------------
// SMEM layout: A 3 stages x 32KB | B hi 64KB | B lo 64KB | red 2KB
// ---------------------------------------------------------------------------
#define SM_BHI  98304u
#define SM_BLO  163840u
#define SM_RED  229376u
#define SM_DYN  231424

// ---------------------------------------------------------------------------
// Weight prep (combined weights -> bf16 hi/lo, swizzled smem image)
// ---------------------------------------------------------------------------
__global__ void prep_w_kernel(const float* __restrict__ wr,
                              const float* __restrict__ wi,
                              const float* __restrict__ cw,
                              unsigned short* __restrict__ whi,
                              unsigned short* __restrict__ wlo)
{
    int idx = blockIdx.x * blockDim.x + threadIdx.x;   // < 131072
    int l = idx >> 15;
    int rem = idx & 32767;
    int kc = rem >> 13;
    int rem2 = rem & 8191;
    int o = rem2 >> 6;
    int kl = rem2 & 63;
    int kg = kc * 64 + kl;
    const float* wrl = wr + (size_t)l * 16384;
    const float* wil = wi + (size_t)l * 16384;
    float v;
    if (kg < 128)
        v = cw[(size_t)l * 16384 + o * 128 + kg] + 0.5f * (wrl[kg * 128 + o] + wil[kg * 128 + o]);
    else {
        int i = kg - 128;
        v = 0.5f * (wrl[i * 128 + o] - wil[i * 128 + o]);
    }
    uint32_t u = __float_as_uint(v);
    float hf = __uint_as_float(u & 0xffff0000u);
    float lo = v - hf;
    uint32_t off = (uint32_t)o * 128 + kl * 2;
    off ^= (off >> 3) & 0x70;
    size_t cbase = (size_t)(l * 4 + kc) * 8192;
    whi[cbase + (off >> 1)] = (unsigned short)(u >> 16);
    __nv_bfloat16 lb = __float2bfloat16_rn(lo);
    wlo[cbase + (off >> 1)] = __bfloat16_as_ushort(lb);
}

// Closed-form Dirichlet: s(x) = -(1/128) * sum_{k=1}^{127} sin(pi*k*x/128)
__global__ void prep_sx_kernel(float* __restrict__ sx)
{
    int x = threadIdx.x;
    double s = 0.0;
    if (x) {
        double th = M_PI * (double)x / 128.0;
        s = sin(63.5 * th) * sin(64.0 * th) / sin(0.5 * th);
    }
    sx[x] = (float)(-s / 128.0);
}

// ---------------------------------------------------------------------------
// Input transform -> bf16 hi/lo buffers
// ---------------------------------------------------------------------------
__global__ void in_kernel(const float* __restrict__ x,
                          const float* __restrict__ w,
                          const float* __restrict__ bias,
                          unsigned short* __restrict__ oh,
                          unsigned short* __restrict__ ol)
{
    int gid = blockIdx.x * blockDim.x + threadIdx.x;
    int pix = gid >> 5;
    int c4 = (gid & 31) << 2;
    int b = pix >> 16;
    int yx = pix & 65535;
    const float* xb = x + (size_t)b * 196608 + yx;
    float x0 = __ldg(xb);
    float x1 = __ldg(xb + 65536);
    float x2 = __ldg(xb + 131072);
    float4 w0 = __ldg((const float4*)(w + c4));
    float4 w1 = __ldg((const float4*)(w + 128 + c4));
    float4 w2 = __ldg((const float4*)(w + 256 + c4));
    float4 bb = __ldg((const float4*)(bias + c4));
    float4 o;
    o.x = gelu_exact(x0 * w0.x + x1 * w1.x + x2 * w2.x + bb.x);
    o.y = gelu_exact(x0 * w0.y + x1 * w1.y + x2 * w2.y + bb.y);
    o.z = gelu_exact(x0 * w0.z + x1 * w1.z + x2 * w2.z + bb.z);
    o.w = gelu_exact(x0 * w0.w + x1 * w1.w + x2 * w2.w + bb.w);
    uint2 hv, lv;
    hv.x = pack_hi2(o.x, o.y); hv.y = pack_hi2(o.z, o.w);
    lv.x = pack_lo2(o.x, o.y); lv.y = pack_lo2(o.z, o.w);
    *(uint2*)((uint32_t*)oh + (size_t)pix * 64 + (c4 >> 1)) = hv;
    *(uint2*)((uint32_t*)ol + (size_t)pix * 64 + (c4 >> 1)) = lv;
}

// ---------------------------------------------------------------------------
// Layer kernel: persistent, 3-stage cp.async, hoisted per-tile addressing
// ---------------------------------------------------------------------------
__global__ void __launch_bounds__(512, 1) layer_kernel(
    const unsigned short* __restrict__ hH, const unsigned short* __restrict__ hL,
    unsigned short* __restrict__ oH, unsigned short* __restrict__ oL,
    const uint4* __restrict__ whiL, const uint4* __restrict__ wloL,
    const float* __restrict__ cbp, const float* __restrict__ brp,
    const float* __restrict__ bip, const float* __restrict__ lowp,
    const float* __restrict__ lobp, float* __restrict__ gout, int fuse)
{
    extern __shared__ char dsm_raw[];
    uint32_t raw = smem_u32(dsm_raw);
    uint32_t sbase = (raw + 127) & ~127u;
    char* sm = dsm_raw + (sbase - raw);

    int tid = threadIdx.x;
    int wid = tid >> 5;
    int lane = tid & 31;
    int wm = wid & 3;        // 4 m-groups x 32 rows
    int wn = wid >> 2;       // 4 n-groups x 32 cols

    // cp.async mapping: m = tid>>2 pixel row, q = tid&3 (16 k each)
    int m = tid >> 2;
    int q = tid & 3;
    uint32_t swz = (uint32_t)(m & 7) << 4;
    uint32_t off0 = (uint32_t)m * 128u + (((uint32_t)q * 32u) ^ swz);
    uint32_t off1 = (uint32_t)m * 128u + (((uint32_t)q * 32u + 16u) ^ swz);
    uint32_t off0l = off0 + 16384u, off1l = off1 + 16384u;
    int qk = q * 16;

    int nloc = (NTILES - blockIdx.x + GRID - 1) / GRID;

    // per-tile pointer builders (executed once per tile, not per chunk)
    auto ptrD = [&](int t, const unsigned short*& pH, const unsigned short*& pL,
                    size_t& base) {
        int b, y, x0;
        decode_tile(t, b, y, x0);
        base = ((size_t)(b * 256 + y)) * 256 + x0;
        size_t e = (base + m) * 128 + qk;
        pH = hH + e;
        pL = hL + e;
    };
    auto ptrF = [&](int t, const unsigned short*& pH, const unsigned short*& pL) {
        int b, y, x0;
        decode_tile(t, b, y, x0);
        int yf = (256 - y) & 255;
        int xf = (256 - (x0 + m)) & 255;
        size_t e = (((size_t)(b * 256 + yf)) * 256 + xf) * 128 + qk;
        pH = hH + e;
        pL = hL + e;
    };

    uint32_t stIssue = 0;   // stage for next issue
    auto issue = [&](const unsigned short* pH, const unsigned short* pL, int koff) {
        uint32_t stb = sbase + stIssue * 32768u;
        CP16(stb + off0,  pH + koff);
        CP16(stb + off1,  pH + koff + 8);
        CP16(stb + off0l, pL + koff);
        CP16(stb + off1l, pL + koff + 8);
        CP_COMMIT();
        stIssue = (stIssue == 2) ? 0 : stIssue + 1;
    };
    auto issue_empty = [&]() {
        CP_COMMIT();
        stIssue = (stIssue == 2) ? 0 : stIssue + 1;
    };

    // ---- prologue: issue tile0 chunks 0,1; load B while they fly ----
    const unsigned short *pDH, *pDL, *pFH, *pFL, *pD2H, *pD2L;
    size_t baseCur, baseNext;
    ptrD(blockIdx.x, pDH, pDL, baseCur);
    issue(pDH, pDL, 0);
    issue(pDH, pDL, 64);
    {
        uint4* bh = (uint4*)(sm + SM_BHI);
        uint4* bl = (uint4*)(sm + SM_BLO);
        #pragma unroll
        for (int qq = 0; qq < 8; qq++) {
            bh[tid + qq * 512] = __ldg(whiL + tid + qq * 512);
            bl[tid + qq * 512] = __ldg(wloL + tid + qq * 512);
        }
    }
    __syncthreads();

    // ldmatrix per-lane address components
    int grp = lane >> 3, lr = lane & 7;
    uint32_t xm = (uint32_t)(lr << 4);
    uint32_t a_rowadd = (uint32_t)(lr + ((grp & 1) << 3));
    uint32_t a_c16 = (uint32_t)((grp >> 1) << 4);
    uint32_t b_rowadd = (uint32_t)(lr + ((grp >> 1) << 3));
    uint32_t b_c16 = (uint32_t)((grp & 1) << 4);
    uint32_t arow[2], brow[2];
    #pragma unroll
    for (int mt = 0; mt < 2; mt++) arow[mt] = (uint32_t)(wm * 32 + mt * 16 + a_rowadd) * 128u;
    #pragma unroll
    for (int np = 0; np < 2; np++) brow[np] = (uint32_t)(wn * 32 + np * 16 + b_rowadd) * 128u;

    // hoisted per-thread bias values (n indices fixed)
    float cbv[8];
    #pragma unroll
    for (int nt = 0; nt < 4; nt++) {
        int n = wn * 32 + nt * 8 + (lane & 3) * 2;
        cbv[nt * 2]     = __ldg(cbp + n);
        cbv[nt * 2 + 1] = __ldg(cbp + n + 1);
    }
    float* red = (float*)(sm + SM_RED);

    float acc[2][4][4];
    uint32_t stM = 0;   // MMA stage

    for (int i = 0; i < nloc; i++) {
        int t = blockIdx.x + i * GRID;
        // pointers needed this tile: flip(t) for chunks 2,3; direct(t+GRID) for next
        ptrF(t, pFH, pFL);
        bool haveNext = (i + 1 < nloc);
        if (haveNext) ptrD(t + GRID, pD2H, pD2L, baseNext);

        int b, y, x0;
        decode_tile(t, b, y, x0);
        bool row0 = (y == 0);

        #pragma unroll
        for (int mt = 0; mt < 2; mt++)
            #pragma unroll
            for (int nt = 0; nt < 4; nt++)
                #pragma unroll
                for (int z = 0; z < 4; z++) acc[mt][nt][z] = 0.0f;

        #pragma unroll
        for (int kc = 0; kc < 4; kc++) {
            CP_WAIT1();
            __syncthreads();
            // issue chunk cc+2 (constant schedule)
            if (kc == 0)      issue(pFH, pFL, 0);
            else if (kc == 1) issue(pFH, pFL, 64);
            else if (kc == 2) { if (haveNext) issue(pD2H, pD2L, 0); else issue_empty(); }
            else              { if (haveNext) issue(pD2H, pD2L, 64); else issue_empty(); }

            // ---- MMA over chunk kc from stage stM ----
            uint32_t aHi = sbase + stM * 32768u;
            uint32_t aLo = aHi + 16384u;
            uint32_t bHi = sbase + SM_BHI + (uint32_t)kc * 16384u;
            uint32_t bLo = sbase + SM_BLO + (uint32_t)kc * 16384u;
            stM = (stM == 2) ? 0 : stM + 1;

            #pragma unroll
            for (int ks = 0; ks < 4; ks++) {
                uint32_t acb = ((uint32_t)(ks * 32) + a_c16) ^ xm;
                uint32_t bcb = ((uint32_t)(ks * 32) + b_c16) ^ xm;
                uint32_t ah[2][4], al[2][4], bh[2][4], bl[2][4];
                #pragma unroll
                for (int mt = 0; mt < 2; mt++) {
                    ldsm4(ah[mt][0], ah[mt][1], ah[mt][2], ah[mt][3], aHi + arow[mt] + acb);
                    ldsm4(al[mt][0], al[mt][1], al[mt][2], al[mt][3], aLo + arow[mt] + acb);
                }
                #pragma unroll
                for (int np = 0; np < 2; np++) {
                    ldsm4(bh[np][0], bh[np][1], bh[np][2], bh[np][3], bHi + brow[np] + bcb);
                    ldsm4(bl[np][0], bl[np][1], bl[np][2], bl[np][3], bLo + brow[np] + bcb);
                }
                #pragma unroll
                for (int np = 0; np < 2; np++)
                    #pragma unroll
                    for (int mt = 0; mt < 2; mt++) {
                        mma16816(acc[mt][np * 2],     ah[mt], bh[np][0], bh[np][1]);
                        mma16816(acc[mt][np * 2 + 1], ah[mt], bh[np][2], bh[np][3]);
                    }
                #pragma unroll
                for (int np = 0; np < 2; np++)
                    #pragma unroll
                    for (int mt = 0; mt < 2; mt++) {
                        mma16816(acc[mt][np * 2],     ah[mt], bl[np][0], bl[np][1]);
                        mma16816(acc[mt][np * 2 + 1], ah[mt], bl[np][2], bl[np][3]);
                    }
                #pragma unroll
                for (int np = 0; np < 2; np++)
                    #pragma unroll
                    for (int mt = 0; mt < 2; mt++) {
                        mma16816(acc[mt][np * 2],     al[mt], bh[np][0], bh[np][1]);
                        mma16816(acc[mt][np * 2 + 1], al[mt], bh[np][2], bh[np][3]);
                    }
            }
        }

        // ---- epilogue for tile t ----
        if (!fuse) {
            #pragma unroll
            for (int mt = 0; mt < 2; mt++) {
                #pragma unroll
                for (int rh = 0; rh < 2; rh++) {
                    int mm = wm * 32 + mt * 16 + (lane >> 2) + rh * 8;
                    int xx = x0 + mm;
                    float sxv = row0 ? __ldg(&g_sx[xx]) : 0.0f;
                    size_t pix = baseCur + mm;
                    uint32_t* rowH = (uint32_t*)oH + pix * 64;
                    uint32_t* rowL = (uint32_t*)oL + pix * 64;
                    #pragma unroll
                    for (int nt = 0; nt < 4; nt++) {
                        int n = wn * 32 + nt * 8 + (lane & 3) * 2;
                        float v0 = acc[mt][nt][rh * 2]     + cbv[nt * 2];
                        float v1 = acc[mt][nt][rh * 2 + 1] + cbv[nt * 2 + 1];
                        if (row0) {
                            v0 += __ldg(bip + n) * sxv;
                            v1 += __ldg(bip + n + 1) * sxv;
                            if (xx == 0) { v0 += __ldg(brp + n); v1 += __ldg(brp + n + 1); }
                        }
                        float g0 = gelu_exact(v0);
                        float g1 = gelu_exact(v1);
                        rowH[n >> 1] = pack_hi2(g0, g1);
                        rowL[n >> 1] = pack_lo2(g0, g1);
                    }
                }
            }
        } else {
            // fused: out[pix] = gelu( sum_n gelu(v_n)*low[n] + lob )
            #pragma unroll
            for (int mt = 0; mt < 2; mt++) {
                #pragma unroll
                for (int rh = 0; rh < 2; rh++) {
                    int mm = wm * 32 + mt * 16 + (lane >> 2) + rh * 8;
                    int xx = x0 + mm;
                    float sxv = row0 ? __ldg(&g_sx[xx]) : 0.0f;
                    float p = 0.0f;
                    #pragma unroll
                    for (int nt = 0; nt < 4; nt++) {
                        int n = wn * 32 + nt * 8 + (lane & 3) * 2;
                        float v0 = acc[mt][nt][rh * 2]     + cbv[nt * 2];
                        float v1 = acc[mt][nt][rh * 2 + 1] + cbv[nt * 2 + 1];
                        if (row0) {
                            v0 += __ldg(bip + n) * sxv;
                            v1 += __ldg(bip + n + 1) * sxv;
                            if (xx == 0) { v0 += __ldg(brp + n); v1 += __ldg(brp + n + 1); }
                        }
                        p += gelu_exact(v0) * __ldg(lowp + n)
                           + gelu_exact(v1) * __ldg(lowp + n + 1);
                    }
                    p += __shfl_xor_sync(0xffffffffu, p, 1);
                    p += __shfl_xor_sync(0xffffffffu, p, 2);
                    if ((lane & 3) == 0) red[wn * 128 + mm] = p;
                }
            }
            __syncthreads();
            if (tid < 128) {
                float s = red[tid] + red[128 + tid] + red[256 + tid] + red[384 + tid];
                gout[baseCur + tid] = gelu_exact(s + __ldg(lobp));
            }
        }
        baseCur = baseNext;
    }
}

// ---------------------------------------------------------------------------
extern "C" void kernel_launch(void* const* d_in, const int* in_sizes, int n_in,
                              void* d_out, int out_size)
{
    const float* x   = (const float*)d_in[0];
    const float* liw = (const float*)d_in[1];
    const float* lib = (const float*)d_in[2];
    const float* wr  = (const float*)d_in[3];
    const float* wi  = (const float*)d_in[4];
    const float* br  = (const float*)d_in[5];
    const float* bi  = (const float*)d_in[6];
    const float* cw  = (const float*)d_in[7];
    const float* cb  = (const float*)d_in[8];
    const float* low = (const float*)d_in[9];
    const float* lob = (const float*)d_in[10];
    float* out = (float*)d_out;

    unsigned short *h0, *l0, *h1, *l1, *whi, *wlo;
    float* sx;
    cudaGetSymbolAddress((void**)&h0, g_h0);
    cudaGetSymbolAddress((void**)&l0, g_l0);
    cudaGetSymbolAddress((void**)&h1, g_h1);
    cudaGetSymbolAddress((void**)&l1, g_l1);
    cudaGetSymbolAddress((void**)&whi, g_whi);
    cudaGetSymbolAddress((void**)&wlo, g_wlo);
    cudaGetSymbolAddress((void**)&sx, g_sx);

    cudaFuncSetAttribute(layer_kernel, cudaFuncAttributeMaxDynamicSharedMemorySize, SM_DYN);

    prep_w_kernel<<<512, 256>>>(wr, wi, cw, whi, wlo);
    prep_sx_kernel<<<1, 256>>>(sx);
    in_kernel<<<NPIX * 32 / 256, 256>>>(x, liw, lib, h0, l0);

    unsigned short* hs[2] = { h0, h1 };
    unsigned short* ls[2] = { l0, l1 };
    for (int l = 0; l < NL; l++) {
        int fuse = (l == NL - 1) ? 1 : 0;
        layer_kernel<<<GRID, 512, SM_DYN>>>(
            hs[l & 1], ls[l & 1], hs[(l & 1) ^ 1], ls[(l & 1) ^ 1],
            (const uint4*)(whi + (size_t)l * 4 * 8192),
            (const uint4*)(wlo + (size_t)l * 4 * 8192),
            cb + l * HID, br + l * HID, bi + l * HID,
            low, lob, out, fuse);
    }
}

// round 11
// speedup vs baseline: 1.7475x; 1.4414x over previous
#include <cuda_runtime.h>
#include <cuda_bf16.h>
#include <math.h>
#include <stdint.h>

#define HID 128
#define NL 4
#define TPI 258
#define NTILE_TOT (TPI*4)
#define GRID 152
#define PART 16908288              // 1032*128*128 elements per component

__device__ unsigned short g_act0[4*(size_t)PART];
__device__ unsigned short g_act1[4*(size_t)PART];
__device__ unsigned short g_wimg[NL * 65536];
__device__ float g_sx[256];

__device__ __forceinline__ uint32_t smem_u32(const void* p) {
    uint32_t a;
    asm("{ .reg .u64 t; cvta.to.shared.u64 t, %1; cvt.u32.u64 %0, t; }" : "=r"(a) : "l"(p));
    return a;
}
__device__ __forceinline__ void ldsm4(uint32_t& r0, uint32_t& r1, uint32_t& r2, uint32_t& r3, uint32_t addr) {
    asm volatile("ldmatrix.sync.aligned.m8n8.x4.shared.b16 {%0,%1,%2,%3}, [%4];"
        : "=r"(r0), "=r"(r1), "=r"(r2), "=r"(r3) : "r"(addr));
}
__device__ __forceinline__ void mma16816(float* d, const uint32_t* a, uint32_t b0, uint32_t b1) {
    asm volatile("mma.sync.aligned.m16n8k16.row.col.f32.bf16.bf16.f32 "
        "{%0,%1,%2,%3}, {%4,%5,%6,%7}, {%8,%9}, {%0,%1,%2,%3};"
        : "+f"(d[0]), "+f"(d[1]), "+f"(d[2]), "+f"(d[3])
        : "r"(a[0]), "r"(a[1]), "r"(a[2]), "r"(a[3]), "r"(b0), "r"(b1));
}
#define CP16(dst, src) asm volatile("cp.async.cg.shared.global [%0], [%1], 16;" :: "r"(dst), "l"(src))
#define CP_COMMIT()    asm volatile("cp.async.commit_group;" ::: "memory")
#define CP_WAIT1()     asm volatile("cp.async.wait_group 1;" ::: "memory")

__device__ __forceinline__ float gelu_exact(float v) {
    return 0.5f * v * (1.0f + erff(v * 0.70710678118654752f));
}
__device__ __forceinline__ uint32_t pack_hi2(float a, float b) {
    return __byte_perm(__float_as_uint(a), __float_as_uint(b), 0x7632);
}
__device__ __forceinline__ uint32_t pack_lo2(float a, float b) {
    float ra = a - __uint_as_float(__float_as_uint(a) & 0xffff0000u);
    float rb = b - __uint_as_float(__float_as_uint(b) & 0xffff0000u);
    __nv_bfloat162 p = __floats2bfloat162_rn(ra, rb);
    return *reinterpret_cast<uint32_t*>(&p);
}
__device__ __forceinline__ void decode_ctile(int tt, int& r, int& x0) {
    if (tt < 254)      { r = 1 + (tt >> 1); x0 = (tt & 1) << 7; }
    else if (tt < 256) { r = 0;             x0 = (tt - 254) << 7; }
    else               { r = 128;           x0 = (tt - 256) << 7; }
}

// one k64 chunk of one GEMM bank (3-combo bf16 split, A-frag regs reused)
__device__ __forceinline__ void mma_chunk(
    float (&acc)[2][4][4], uint32_t aHi, uint32_t bHi,
    const uint32_t (&arow)[2], const uint32_t (&brow)[2],
    uint32_t a_c16, uint32_t b_c16, uint32_t xm)
{
    uint32_t aLo = aHi + 16384u;
    uint32_t bLo = bHi + 32768u;
    #pragma unroll
    for (int ks = 0; ks < 4; ks++) {
        uint32_t acb = ((uint32_t)(ks * 32) + a_c16) ^ xm;
        uint32_t bcb = ((uint32_t)(ks * 32) + b_c16) ^ xm;
        uint32_t af[2][4], bh[2][4], bl[2][4];
        #pragma unroll
        for (int mt = 0; mt < 2; mt++)
            ldsm4(af[mt][0], af[mt][1], af[mt][2], af[mt][3], aHi + arow[mt] + acb);
        #pragma unroll
        for (int np = 0; np < 2; np++) {
            ldsm4(bh[np][0], bh[np][1], bh[np][2], bh[np][3], bHi + brow[np] + bcb);
            ldsm4(bl[np][0], bl[np][1], bl[np][2], bl[np][3], bLo + brow[np] + bcb);
        }
        #pragma unroll
        for (int np = 0; np < 2; np++)
            #pragma unroll
            for (int mt = 0; mt < 2; mt++) {
                mma16816(acc[mt][np * 2],     af[mt], bh[np][0], bh[np][1]);
                mma16816(acc[mt][np * 2 + 1], af[mt], bh[np][2], bh[np][3]);
            }
        #pragma unroll
        for (int np = 0; np < 2; np++)
            #pragma unroll
            for (int mt = 0; mt < 2; mt++) {
                mma16816(acc[mt][np * 2],     af[mt], bl[np][0], bl[np][1]);
                mma16816(acc[mt][np * 2 + 1], af[mt], bl[np][2], bl[np][3]);
            }
        #pragma unroll
        for (int mt = 0; mt < 2; mt++)
            ldsm4(af[mt][0], af[mt][1], af[mt][2], af[mt][3], aLo + arow[mt] + acb);
        #pragma unroll
        for (int np = 0; np < 2; np++)
            #pragma unroll
            for (int mt = 0; mt < 2; mt++) {
                mma16816(acc[mt][np * 2],     af[mt], bh[np][0], bh[np][1]);
                mma16816(acc[mt][np * 2 + 1], af[mt], bh[np][2], bh[np][3]);
            }
    }
}

// SMEM: A stages 3x32KB @0 | B 128KB @98304 | bias 2KB @229376
#define SM_B    98304u
#define SM_BIAS 229376u
#define SM_DYN  231552

// ---------------------------------------------------------------------------
// Weight prep: As=(cw^T+wr)/2 (sel 0), Ad=(cw^T+wi)/2 (sel 1) -> hi/lo SW128
// ---------------------------------------------------------------------------
__global__ void prep_w_kernel(const float* __restrict__ wr,
                              const float* __restrict__ wi,
                              const float* __restrict__ cw,
                              unsigned short* __restrict__ wimg)
{
    int idx = blockIdx.x * blockDim.x + threadIdx.x;   // < 131072
    int l = idx >> 15;
    int rem = idx & 32767;
    int sel = rem >> 14;
    int rem2 = rem & 16383;
    int kc2 = rem2 >> 13;
    int rem3 = rem2 & 8191;
    int o = rem3 >> 6;
    int kl = rem3 & 63;
    int k = kc2 * 64 + kl;
    const float* wsel = (sel ? wi : wr) + (size_t)l * 16384;
    float v = 0.5f * (cw[(size_t)l * 16384 + o * 128 + k] + wsel[k * 128 + o]);
    uint32_t u = __float_as_uint(v);
    float hf = __uint_as_float(u & 0xffff0000u);
    float lo = v - hf;
    uint32_t off = (uint32_t)o * 128 + kl * 2;
    off ^= (off >> 3) & 0x70;
    size_t base = (size_t)l * 65536 + sel * 32768 + kc2 * 8192;
    wimg[base + (off >> 1)] = (unsigned short)(u >> 16);
    __nv_bfloat16 lb = __float2bfloat16_rn(lo);
    wimg[base + 16384 + (off >> 1)] = __bfloat16_as_ushort(lb);
}

__global__ void prep_sx_kernel(float* __restrict__ sx)
{
    int x = threadIdx.x;
    double s = 0.0;
    if (x) {
        double th = M_PI * (double)x / 128.0;
        s = sin(63.5 * th) * sin(64.0 * th) / sin(0.5 * th);
    }
    sx[x] = (float)(-s / 128.0);
}

// ---------------------------------------------------------------------------
// Input transform -> canonical s/d bf16 hi/lo
// ---------------------------------------------------------------------------
__global__ void in_kernel(const float* __restrict__ x,
                          const float* __restrict__ w,
                          const float* __restrict__ bias,
                          unsigned short* __restrict__ act)
{
    int gid = blockIdx.x * blockDim.x + threadIdx.x;
    int slot = gid >> 5;
    int c4 = (gid & 31) << 2;
    int t = slot >> 7, m = slot & 127;
    int b = t / TPI, tt = t - b * TPI;
    int r, x0;
    decode_ctile(tt, r, x0);
    int xc = x0 + m;
    int rf = (256 - r) & 255, xf = (256 - xc) & 255;
    const float* xb = x + (size_t)b * 196608;
    int ip = r * 256 + xc, iq = rf * 256 + xf;
    float xp0 = __ldg(xb + ip), xp1 = __ldg(xb + ip + 65536), xp2 = __ldg(xb + ip + 131072);
    float xq0 = __ldg(xb + iq), xq1 = __ldg(xb + iq + 65536), xq2 = __ldg(xb + iq + 131072);
    float4 w0 = __ldg((const float4*)(w + c4));
    float4 w1 = __ldg((const float4*)(w + 128 + c4));
    float4 w2 = __ldg((const float4*)(w + 256 + c4));
    float4 bb = __ldg((const float4*)(bias + c4));
    float gp0 = gelu_exact(xp0 * w0.x + xp1 * w1.x + xp2 * w2.x + bb.x);
    float gp1 = gelu_exact(xp0 * w0.y + xp1 * w1.y + xp2 * w2.y + bb.y);
    float gp2 = gelu_exact(xp0 * w0.z + xp1 * w1.z + xp2 * w2.z + bb.z);
    float gp3 = gelu_exact(xp0 * w0.w + xp1 * w1.w + xp2 * w2.w + bb.w);
    float gf0 = gelu_exact(xq0 * w0.x + xq1 * w1.x + xq2 * w2.x + bb.x);
    float gf1 = gelu_exact(xq0 * w0.y + xq1 * w1.y + xq2 * w2.y + bb.y);
    float gf2 = gelu_exact(xq0 * w0.z + xq1 * w1.z + xq2 * w2.z + bb.z);
    float gf3 = gelu_exact(xq0 * w0.w + xq1 * w1.w + xq2 * w2.w + bb.w);
    float s0 = gp0 + gf0, s1 = gp1 + gf1, s2 = gp2 + gf2, s3 = gp3 + gf3;
    float d0 = gp0 - gf0, d1 = gp1 - gf1, d2 = gp2 - gf2, d3 = gp3 - gf3;
    size_t wb = (size_t)slot * 64 + (c4 >> 1);
    uint32_t* aSH = (uint32_t*)act;
    uint32_t* aSL = aSH + (PART >> 1);
    uint32_t* aDH = aSH + PART;
    uint32_t* aDL = aDH + (PART >> 1);
    uint2 v;
    v.x = pack_hi2(s0, s1); v.y = pack_hi2(s2, s3); *(uint2*)(aSH + wb) = v;
    v.x = pack_lo2(s0, s1); v.y = pack_lo2(s2, s3); *(uint2*)(aSL + wb) = v;
    v.x = pack_hi2(d0, d1); v.y = pack_hi2(d2, d3); *(uint2*)(aDH + wb) = v;
    v.x = pack_lo2(d0, d1); v.y = pack_lo2(d2, d3); *(uint2*)(aDL + wb) = v;
}

// ---------------------------------------------------------------------------
// Layer kernel: symmetric/antisymmetric pair GEMM (P = s*As, Q = d*Ad)
// ---------------------------------------------------------------------------
__global__ void __launch_bounds__(512, 1) layer_kernel(
    const unsigned short* __restrict__ actIn,
    unsigned short* __restrict__ actOut,
    const uint4* __restrict__ wimgL,
    const float* __restrict__ cbp, const float* __restrict__ brp,
    const float* __restrict__ bip, const float* __restrict__ lowp,
    const float* __restrict__ lobp, float* __restrict__ gout, int fuse)
{
    extern __shared__ char dsm_raw[];
    uint32_t raw = smem_u32(dsm_raw);
    uint32_t sbase = (raw + 127) & ~127u;
    char* sm = dsm_raw + (sbase - raw);

    int tid = threadIdx.x, wid = tid >> 5, lane = tid & 31;
    int wm = wid & 3, wn = wid >> 2;

    int m = tid >> 2, q = tid & 3;
    uint32_t swz = (uint32_t)(m & 7) << 4;
    uint32_t off0 = (uint32_t)m * 128u + (((uint32_t)q * 32u) ^ swz);
    uint32_t off1 = (uint32_t)m * 128u + (((uint32_t)q * 32u + 16u) ^ swz);
    uint32_t off0l = off0 + 16384u, off1l = off1 + 16384u;

    size_t thOff = ((size_t)blockIdx.x * 128 + m) * 128 + q * 16;
    const unsigned short* pSH = actIn + thOff;
    const unsigned short* pSL = pSH + PART;
    const unsigned short* pDH = pSH + 2 * (size_t)PART;
    const unsigned short* pDL = pSH + 3 * (size_t)PART;
    const size_t TSTR = (size_t)GRID * 16384;

    int nloc = (NTILE_TOT - blockIdx.x + GRID - 1) / GRID;

    uint32_t stI = 0;
    #define ISSUE4(PH, PL, K0) do { \
        uint32_t stb = sbase + stI * 32768u; \
        CP16(stb + off0,  (PH) + (K0)); CP16(stb + off1,  (PH) + (K0) + 8); \
        CP16(stb + off0l, (PL) + (K0)); CP16(stb + off1l, (PL) + (K0) + 8); \
        CP_COMMIT(); stI = (stI == 2) ? 0 : stI + 1; } while (0)
    #define ISSUE_NONE() do { CP_COMMIT(); stI = (stI == 2) ? 0 : stI + 1; } while (0)

    ISSUE4(pSH, pSL, 0);
    ISSUE4(pSH, pSL, 64);
    {
        uint4* bs = (uint4*)(sm + SM_B);
        #pragma unroll
        for (int qq = 0; qq < 16; qq++)
            bs[tid + qq * 512] = __ldg(wimgL + tid + qq * 512);
        float* bf = (float*)(sm + SM_BIAS);
        if (tid < 128) {
            bf[tid]       = __ldg(cbp + tid);
            bf[128 + tid] = __ldg(brp + tid);
            bf[256 + tid] = __ldg(bip + tid);
            bf[384 + tid] = __ldg(lowp + tid);
        }
    }
    __syncthreads();

    int grp = lane >> 3, lr = lane & 7;
    uint32_t xm = (uint32_t)(lr << 4);
    uint32_t a_c16 = (uint32_t)((grp >> 1) << 4);
    uint32_t b_c16 = (uint32_t)((grp & 1) << 4);
    uint32_t arow[2], brow[2];
    #pragma unroll
    for (int mt = 0; mt < 2; mt++)
        arow[mt] = (uint32_t)(wm * 32 + mt * 16 + lr + ((grp & 1) << 3)) * 128u;
    #pragma unroll
    for (int np = 0; np < 2; np++)
        brow[np] = (uint32_t)(wn * 32 + np * 16 + lr + ((grp >> 1) << 3)) * 128u;

    const float* cbS  = (const float*)(sm + SM_BIAS);
    const float* brS  = cbS + 128;
    const float* biS  = cbS + 256;
    const float* lowS = cbS + 384;

    uint32_t stM = 0;
    for (int i = 0; i < nloc; i++) {
        int t = blockIdx.x + i * GRID;
        int b = t / TPI, tt = t - b * TPI;
        int r, x0;
        decode_ctile(tt, r, x0);
        bool haveNext = (i + 1 < nloc);
        bool row0 = (r == 0);

        float accP[2][4][4], accQ[2][4][4];
        #pragma unroll
        for (int mt = 0; mt < 2; mt++)
            #pragma unroll
            for (int nt = 0; nt < 4; nt++)
                #pragma unroll
                for (int z = 0; z < 4; z++) { accP[mt][nt][z] = 0.0f; accQ[mt][nt][z] = 0.0f; }

        // chunk 0: P += s(k0..63) * As(k0)
        CP_WAIT1(); __syncthreads();
        ISSUE4(pDH, pDL, 0);
        mma_chunk(accP, sbase + stM * 32768u, sbase + SM_B, arow, brow, a_c16, b_c16, xm);
        stM = (stM == 2) ? 0 : stM + 1;
        // chunk 1: P += s(k64..127) * As(k1)
        CP_WAIT1(); __syncthreads();
        ISSUE4(pDH, pDL, 64);
        mma_chunk(accP, sbase + stM * 32768u, sbase + SM_B + 16384u, arow, brow, a_c16, b_c16, xm);
        stM = (stM == 2) ? 0 : stM + 1;
        // chunk 2: Q += d(k0..63) * Ad(k0)
        CP_WAIT1(); __syncthreads();
        if (haveNext) ISSUE4(pSH + TSTR, pSL + TSTR, 0); else ISSUE_NONE();
        mma_chunk(accQ, sbase + stM * 32768u, sbase + SM_B + 65536u, arow, brow, a_c16, b_c16, xm);
        stM = (stM == 2) ? 0 : stM + 1;
        // chunk 3: Q += d(k64..127) * Ad(k1)
        CP_WAIT1(); __syncthreads();
        if (haveNext) ISSUE4(pSH + TSTR, pSL + TSTR, 64); else ISSUE_NONE();
        uint32_t stEpi = stM;
        mma_chunk(accQ, sbase + stM * 32768u, sbase + SM_B + 81920u, arow, brow, a_c16, b_c16, xm);
        stM = (stM == 2) ? 0 : stM + 1;

        if (!fuse) {
            uint32_t* oSH = (uint32_t*)actOut + (size_t)t * 8192;
            uint32_t* oSL = oSH + (PART >> 1);
            uint32_t* oDH = oSH + PART;
            uint32_t* oDL = oDH + (PART >> 1);
            #pragma unroll
            for (int mt = 0; mt < 2; mt++) {
                #pragma unroll
                for (int rh = 0; rh < 2; rh++) {
                    int mm = wm * 32 + mt * 16 + (lane >> 2) + rh * 8;
                    int xc = x0 + mm;
                    int xf = (256 - xc) & 255;
                    float sxp = row0 ? __ldg(&g_sx[xc]) : 0.0f;
                    float sxf = row0 ? __ldg(&g_sx[xf]) : 0.0f;
                    uint32_t ob = (uint32_t)mm * 64;
                    #pragma unroll
                    for (int nt = 0; nt < 4; nt++) {
                        int n = wn * 32 + nt * 8 + (lane & 3) * 2;
                        float P0 = accP[mt][nt][rh * 2], P1 = accP[mt][nt][rh * 2 + 1];
                        float Q0 = accQ[mt][nt][rh * 2], Q1 = accQ[mt][nt][rh * 2 + 1];
                        float c0 = cbS[n], c1 = cbS[n + 1];
                        float up0 = P0 + Q0 + c0, up1 = P1 + Q1 + c1;
                        float uf0 = P0 - Q0 + c0, uf1 = P1 - Q1 + c1;
                        if (row0) {
                            float b0 = biS[n], b1 = biS[n + 1];
                            up0 += b0 * sxp; up1 += b1 * sxp;
                            uf0 += b0 * sxf; uf1 += b1 * sxf;
                            if (xc == 0) {
                                up0 += brS[n]; up1 += brS[n + 1];
                                uf0 += brS[n]; uf1 += brS[n + 1];
                            }
                        }
                        float gp0 = gelu_exact(up0), gp1 = gelu_exact(up1);
                        float gf0 = gelu_exact(uf0), gf1 = gelu_exact(uf1);
                        float s0 = gp0 + gf0, s1 = gp1 + gf1;
                        float d0 = gp0 - gf0, d1 = gp1 - gf1;
                        uint32_t w = ob + (n >> 1);
                        oSH[w] = pack_hi2(s0, s1); oSL[w] = pack_lo2(s0, s1);
                        oDH[w] = pack_hi2(d0, d1); oDL[w] = pack_lo2(d0, d1);
                    }
                }
            }
        } else {
            float* red = (float*)(sm + stEpi * 32768u);
            float ppv[2][2], pfv[2][2];
            #pragma unroll
            for (int mt = 0; mt < 2; mt++) {
                #pragma unroll
                for (int rh = 0; rh < 2; rh++) {
                    int mm = wm * 32 + mt * 16 + (lane >> 2) + rh * 8;
                    int xc = x0 + mm;
                    int xf = (256 - xc) & 255;
                    float sxp = row0 ? __ldg(&g_sx[xc]) : 0.0f;
                    float sxf = row0 ? __ldg(&g_sx[xf]) : 0.0f;
                    float pp = 0.0f, pf = 0.0f;
                    #pragma unroll
                    for (int nt = 0; nt < 4; nt++) {
                        int n = wn * 32 + nt * 8 + (lane & 3) * 2;
                        float P0 = accP[mt][nt][rh * 2], P1 = accP[mt][nt][rh * 2 + 1];
                        float Q0 = accQ[mt][nt][rh * 2], Q1 = accQ[mt][nt][rh * 2 + 1];
                        float c0 = cbS[n], c1 = cbS[n + 1];
                        float up0 = P0 + Q0 + c0, up1 = P1 + Q1 + c1;
                        float uf0 = P0 - Q0 + c0, uf1 = P1 - Q1 + c1;
                        if (row0) {
                            float b0 = biS[n], b1 = biS[n + 1];
                            up0 += b0 * sxp; up1 += b1 * sxp;
                            uf0 += b0 * sxf; uf1 += b1 * sxf;
                            if (xc == 0) {
                                up0 += brS[n]; up1 += brS[n + 1];
                                uf0 += brS[n]; uf1 += brS[n + 1];
                            }
                        }
                        pp += gelu_exact(up0) * lowS[n] + gelu_exact(up1) * lowS[n + 1];
                        pf += gelu_exact(uf0) * lowS[n] + gelu_exact(uf1) * lowS[n + 1];
                    }
                    pp += __shfl_xor_sync(0xffffffffu, pp, 1);
                    pp += __shfl_xor_sync(0xffffffffu, pp, 2);
                    pf += __shfl_xor_sync(0xffffffffu, pf, 1);
                    pf += __shfl_xor_sync(0xffffffffu, pf, 2);
                    ppv[mt][rh] = pp; pfv[mt][rh] = pf;
                }
            }
            __syncthreads();
            if ((lane & 3) == 0) {
                #pragma unroll
                for (int mt = 0; mt < 2; mt++)
                    #pragma unroll
                    for (int rh = 0; rh < 2; rh++) {
                        int mm = wm * 32 + mt * 16 + (lane >> 2) + rh * 8;
                        red[wn * 128 + mm] = ppv[mt][rh];
                        red[512 + wn * 128 + mm] = pfv[mt][rh];
                    }
            }
            __syncthreads();
            if (tid < 128) {
                float lob = __ldg(lobp);
                float sp = red[tid] + red[128 + tid] + red[256 + tid] + red[384 + tid];
                float sf = red[512 + tid] + red[640 + tid] + red[768 + tid] + red[896 + tid];
                int xc = x0 + tid, xf = (256 - xc) & 255, rf = (256 - r) & 255;
                gout[(size_t)b * 65536 + r * 256 + xc]   = gelu_exact(sp + lob);
                gout[(size_t)b * 65536 + rf * 256 + xf]  = gelu_exact(sf + lob);
            }
            __syncthreads();
        }
        pSH += TSTR; pSL += TSTR; pDH += TSTR; pDL += TSTR;
    }
}

// ---------------------------------------------------------------------------
extern "C" void kernel_launch(void* const* d_in, const int* in_sizes, int n_in,
                              void* d_out, int out_size)
{
    const float* x   = (const float*)d_in[0];
    const float* liw = (const float*)d_in[1];
    const float* lib = (const float*)d_in[2];
    const float* wr  = (const float*)d_in[3];
    const float* wi  = (const float*)d_in[4];
    const float* br  = (const float*)d_in[5];
    const float* bi  = (const float*)d_in[6];
    const float* cw  = (const float*)d_in[7];
    const float* cb  = (const float*)d_in[8];
    const float* low = (const float*)d_in[9];
    const float* lob = (const float*)d_in[10];
    float* out = (float*)d_out;

    unsigned short *a0, *a1, *wimg;
    float* sx;
    cudaGetSymbolAddress((void**)&a0, g_act0);
    cudaGetSymbolAddress((void**)&a1, g_act1);
    cudaGetSymbolAddress((void**)&wimg, g_wimg);
    cudaGetSymbolAddress((void**)&sx, g_sx);

    cudaFuncSetAttribute(layer_kernel, cudaFuncAttributeMaxDynamicSharedMemorySize, SM_DYN);

    prep_w_kernel<<<512, 256>>>(wr, wi, cw, wimg);
    prep_sx_kernel<<<1, 256>>>(sx);
    in_kernel<<<NTILE_TOT * 128 * 32 / 256, 256>>>(x, liw, lib, a0);

    unsigned short* as[2] = { a0, a1 };
    for (int l = 0; l < NL; l++) {
        int fuse = (l == NL - 1) ? 1 : 0;
        layer_kernel<<<GRID, 512, SM_DYN>>>(
            as[l & 1], as[(l & 1) ^ 1],
            (const uint4*)(wimg + (size_t)l * 65536),
            cb + l * HID, br + l * HID, bi + l * HID,
            low, lob, out, fuse);
    }
}